// round 11
// baseline (speedup 1.0000x reference)
#include <cuda_runtime.h>
#include <math.h>

#define BATCH  128
#define LATENT 256
#define HIDDEN 512
#define MNODES 64
#define NPAIRS 2016
#define G3     1536
#define HB     65536

typedef unsigned long long u64;

// ---------------- device scratch (zero-initialized at load) ----------------
__device__ __align__(16) float g_Cm [MNODES*LATENT];
__device__ __align__(16) float g_zWT[LATENT*BATCH];
__device__ __align__(16) float g_AT [G3*BATCH];        // [g][b]
__device__ __align__(16) float g_D  [MNODES*G3];       // [t][g]
__device__ __align__(16) float g_PQt[HIDDEN*1024];     // [k][h'] P|Q transposed
__device__ __align__(16) float g_h1T[MNODES*HB];       // [t][k][b]
__device__ __align__(16) float g_h2T[MNODES*HB];       // [t][k][b]
__device__ __align__(16) float g_zH [HB];              // stays all-zero
__device__ __align__(16) float g_U  [BATCH*MNODES*HIDDEN];
__device__ __align__(16) float g_V  [BATCH*MNODES*HIDDEN];
__device__ int g_ii[NPAIRS];
__device__ int g_jj[NPAIRS];
__device__ unsigned g_bar_cnt;   // monotonic ticket counter (never reset)

// ---------------- f32x2 helpers (lanes = independent IEEE fma chains) ------
__device__ __forceinline__ u64 pack2(float x){u64 r;asm("mov.b64 %0,{%1,%1};":"=l"(r):"f"(x));return r;}
__device__ __forceinline__ void fma2(u64&a,u64 b,u64 c){asm("fma.rn.f32x2 %0, %1, %2, %0;":"+l"(a):"l"(b),"l"(c));}
__device__ __forceinline__ float2 unpk(u64 v){float2 f;asm("mov.b64 {%0,%1},%2;":"=f"(f.x),"=f"(f.y):"l"(v));return f;}
__device__ __forceinline__ u64 packab(float a,float b){u64 r;asm("mov.b64 %0,{%1,%2};":"=l"(r):"f"(a),"f"(b));return r;}
__device__ __forceinline__ float sigm(float x){return 1.f/(1.f+expf(-x));}

// ---------------- ticket grid barrier (replay-safe, no reset needed) -------
__device__ __forceinline__ void gridbar()
{
    __threadfence();
    __syncthreads();
    if (threadIdx.x == 0) {
        unsigned t = atomicAdd(&g_bar_cnt, 1u);
        unsigned target = (t & ~127u) + 128u;
        while (*(volatile unsigned*)&g_bar_cnt < target) {}
        __threadfence();
    }
    __syncthreads();
}

// ---------------- cp.async (L2-only .cg — cross-SM coherent) ---------------
__device__ __forceinline__ void cp16(void* smem, const void* gmem){
    unsigned s = (unsigned)__cvta_generic_to_shared(smem);
    asm volatile("cp.async.cg.shared.global [%0], [%1], 16;" :: "r"(s), "l"(gmem) : "memory");
}
__device__ __forceinline__ void cp_commit(){ asm volatile("cp.async.commit_group;" ::: "memory"); }
__device__ __forceinline__ void cp_wait0(){ asm volatile("cp.async.wait_group 0;" ::: "memory"); }
__device__ __forceinline__ void cp_wait1(){ asm volatile("cp.async.wait_group 1;" ::: "memory"); }
__device__ __forceinline__ void cp_wait2(){ asm volatile("cp.async.wait_group 2;" ::: "memory"); }

// ---------------- generic tiled fp32 GEMM body (ascending-k chain) ---------
template<int BM, int BN, int BK, int TM, int TN, bool A_ROW, bool B_NK>
__device__ __forceinline__ void sgemm_dev(const float* __restrict__ A, const float* __restrict__ B,
                                          float* __restrict__ C, const float* __restrict__ bias,
                                          int K, int lda, int ldb, int ldc, int m0, int n0,
                                          float* sms)
{
    float* As = sms;
    float* Bs = sms + BM * BK;
    constexpr int NTH = (BM / TM) * (BN / TN);
    const int tid  = threadIdx.x;
    const int tcol = tid % (BN / TN);
    const int trow = tid / (BN / TN);
    float acc[TM][TN];
#pragma unroll
    for (int i = 0; i < TM; i++)
#pragma unroll
        for (int jx = 0; jx < TN; jx++) acc[i][jx] = 0.f;
    for (int k0 = 0; k0 < K; k0 += BK) {
#pragma unroll
        for (int idx = tid; idx < BM * BK; idx += NTH) {
            int m = idx / BK, kk = idx % BK;
            As[kk*BM + m] = A_ROW ? A[(long)(m0 + m) * lda + (k0 + kk)]
                                  : A[(long)(k0 + kk) * lda + (m0 + m)];
        }
#pragma unroll
        for (int idx = tid; idx < BK * BN; idx += NTH) {
            int kk = idx / BN, n = idx % BN;
            Bs[kk*BN + n] = B_NK ? B[(long)(n0 + n) * ldb + (k0 + kk)]
                                 : B[(long)(k0 + kk) * ldb + (n0 + n)];
        }
        __syncthreads();
#pragma unroll
        for (int kk = 0; kk < BK; kk++) {
            float a[TM], bb[TN];
#pragma unroll
            for (int i = 0; i < TM; i++) a[i] = As[kk*BM + trow * TM + i];
#pragma unroll
            for (int jx = 0; jx < TN; jx++) bb[jx] = Bs[kk*BN + tcol * TN + jx];
#pragma unroll
            for (int i = 0; i < TM; i++)
#pragma unroll
                for (int jx = 0; jx < TN; jx++)
                    acc[i][jx] = fmaf(a[i], bb[jx], acc[i][jx]);
        }
        __syncthreads();
    }
#pragma unroll
    for (int i = 0; i < TM; i++) {
        int m = m0 + trow * TM + i;
#pragma unroll
        for (int jx = 0; jx < TN; jx++) {
            int n = n0 + tcol * TN + jx;
            float v = acc[i][jx];
            if (bias) v += bias[n];
            C[(long)m * ldc + n] = v;
        }
    }
}

template<int BM, int BN, int BK, int TM, int TN, bool A_ROW, bool B_NK>
__global__ void sgemm_k(const float* __restrict__ A, const float* __restrict__ B,
                        float* __restrict__ C, const float* __restrict__ bias,
                        int K, int lda, int ldb, int ldc)
{
    __shared__ float sms[BM*BK + BK*BN];
    sgemm_dev<BM,BN,BK,TM,TN,A_ROW,B_NK>(A, B, C, bias, K, lda, ldb, ldc,
                                         blockIdx.y*BM, blockIdx.x*BN, sms);
}

// ---------------- prolog fused kernel: AT + D + pairidx --------------------
__global__ void ATD_k(const float* __restrict__ Wih0)
{
    __shared__ float sms[2048];
    int bx = blockIdx.x;
    if (bx < 96) {
        sgemm_dev<64,32,16,4,2,true,false>(Wih0, g_zWT, g_AT, nullptr,
            LATENT, LATENT, BATCH, BATCH, (bx>>2)*64, (bx&3)*32, sms);
    } else if (bx < 120) {
        sgemm_dev<64,64,16,4,4,true,true>(g_Cm, Wih0, g_D, nullptr,
            LATENT, LATENT, LATENT, G3, 0, (bx-96)*64, sms);
    } else {
        for (int p = threadIdx.x; p < NPAIRS; p += 256) {
            int i = 0, rem = p;
            while (rem >= 63 - i) { rem -= 63 - i; i++; }
            g_ii[p] = i;
            g_jj[p] = i + 1 + rem;
        }
    }
}

// ---------------- small precompute kernels ---------------------------------
__global__ void precompC_k(const float* __restrict__ pe, const float* __restrict__ emb,
                           const float* __restrict__ W_pre, const float* __restrict__ b_pre)
{
    int t = blockIdx.x, l = threadIdx.x;
    const float* w = W_pre + l * 512;
    float acc = b_pre[l];
    for (int d = 0; d < 256; d++)
        acc += pe[t * 256 + d] * w[d] + emb[t * 256 + d] * w[256 + d];
    g_Cm[t * 256 + l] = acc;
}

__global__ void precompzW_k(const float* __restrict__ z, const float* __restrict__ W_pre)
{
    int b = blockIdx.x, l = threadIdx.x;
    const float* w = W_pre + l * 512;
    float acc = 0.f;
    for (int d = 0; d < 256; d++)
        acc += z[b * 256 + d] * w[d];
    g_zWT[l * BATCH + b] = acc;
}

__global__ void zero_k(float* p, int n)
{
    int i = blockIdx.x * blockDim.x + threadIdx.x;
    if (i < n) p[i] = 0.f;
}

// ---------------- persistent pipelined 2-layer GRU (512 threads) -----------
// 128 CTAs x 512 thr, 1 CTA/SM. CTA owns j rows bx*4..bx*4+3 for all 3 mats
// (m0=Whh0 reads h1, m1=Wih1 reads h1, m2=Whh1 reads h2).
// Thread: b = tid&127, p = (tid>>7)&1 (j-pair), tg = tid>>8 (warp-group).
//   tg0 owns mg 0..4 = {m0r,m0z,m0n,m1r,m1z}; tg1 owns mg 5..8 = {m1n,m2r,m2z,m2n}.
// Each accumulator is a full ascending-k fma2 chain (bitwise = R9); tg0 hands
// m1r/m1z to tg1 via smem for the gate1 epilogue (pure value move).
// Smem: 72KB packed weight pairs + 4-slot ring of 32KB h-chunks.
__global__ void __launch_bounds__(512, 1)
rnn_pipe(const float* __restrict__ Whh0, const float* __restrict__ Whh1,
         const float* __restrict__ Wih1,
         const float* __restrict__ bih0, const float* __restrict__ bhh0,
         const float* __restrict__ bih1, const float* __restrict__ bhh1,
         const int* __restrict__ n_nodes)
{
    extern __shared__ float sm[];
    u64*   sw2  = (u64*)sm;              // 9216 u64 = 72KB
    float* ring = sm + 18432;            // 4 x 8192 floats = 128KB

    const int tid = threadIdx.x;
    const int bx  = blockIdx.x;
    const int b   = tid & 127;
    const int p   = (tid >> 7) & 1;      // j-pair 0/1
    const int tg  = tid >> 8;            // warp-group 0/1
    const int jA  = bx*4 + 2*p;

    // stage packed weight pairs: row = mg*2 + pr, lanes {j even, j odd}
    for (int i = tid; i < 9216; i += 512) {
        int row = i >> 9, k = i & 511;
        int mg = row >> 1, pr = row & 1;
        int m = mg / 3, g = mg % 3;
        const float* W = (m == 0) ? Whh0 : (m == 1) ? Wih1 : Whh1;
        size_t r0 = (size_t)(g*512 + bx*4 + 2*pr) * 512 + k;
        sw2[i] = packab(W[r0], W[r0 + 512]);
    }
    __syncthreads();
    const u64* w2p = sw2 + p*512;

    // per-thread constants
    float bi0[2][3], bh0[2][3], bi1[2][3], bh1[2][3], at[2][3];
    int nn = 0;
    if (tg == 0) {
        nn = n_nodes[b];
#pragma unroll
        for (int l = 0; l < 2; l++) {
            int j = jA + l;
#pragma unroll
            for (int g = 0; g < 3; g++) {
                bi0[l][g] = bih0[g*512 + j]; bh0[l][g] = bhh0[g*512 + j];
                at[l][g]  = g_AT[(size_t)(g*512 + j)*128 + b];
            }
        }
    } else {
#pragma unroll
        for (int l = 0; l < 2; l++) {
            int j = jA + l;
#pragma unroll
            for (int g = 0; g < 3; g++) {
                bi1[l][g] = bih1[g*512 + j]; bh1[l][g] = bhh1[g*512 + j];
            }
        }
    }
    float h1p[2] = {0.f, 0.f}, h2p[2] = {0.f, 0.f};

    for (int s = 0; s <= 64; s++) {
        const float* b1 = (s >= 1) ? g_h1T + (size_t)(s-1)*HB : g_zH;
        const float* b2 = (s >= 2) ? g_h2T + (size_t)(s-2)*HB : g_zH;
        u64 acc[5] = {0,0,0,0,0};

        // prime ring with chunks 0..2 (32k x 128b of h1 + h2 each)
#pragma unroll
        for (int c0 = 0; c0 < 3; c0++) {
            float* buf = ring + c0*8192;
#pragma unroll
            for (int i = 0; i < 2; i++) {
                cp16(buf + (tid + 512*i)*4,        b1 + (size_t)c0*4096 + (tid + 512*i)*4);
                cp16(buf + 4096 + (tid + 512*i)*4, b2 + (size_t)c0*4096 + (tid + 512*i)*4);
            }
            cp_commit();
        }

        for (int c = 0; c < 16; c++) {
            if (c <= 13) cp_wait2(); else if (c == 14) cp_wait1(); else cp_wait0();
            __syncthreads();
            if (c + 3 < 16) {
                float* buf = ring + ((c+3)&3)*8192;
#pragma unroll
                for (int i = 0; i < 2; i++) {
                    cp16(buf + (tid + 512*i)*4,        b1 + (size_t)(c+3)*4096 + (tid + 512*i)*4);
                    cp16(buf + 4096 + (tid + 512*i)*4, b2 + (size_t)(c+3)*4096 + (tid + 512*i)*4);
                }
                cp_commit();
            }
            const float* sh1 = ring + (c&3)*8192;
            const float* sh2 = sh1 + 4096;
            const int kbase = c*32;
            if (tg == 0) {
#pragma unroll 8
                for (int kk = 0; kk < 32; kk += 2) {
                    ulonglong2 wv[5];
#pragma unroll
                    for (int mg = 0; mg < 5; mg++)
                        wv[mg] = *(const ulonglong2*)(w2p + mg*1024 + kbase + kk);
                    u64 pa = pack2(sh1[kk*128 + b]);
                    u64 pb = pack2(sh1[(kk+1)*128 + b]);
#pragma unroll
                    for (int mg = 0; mg < 5; mg++) {
                        fma2(acc[mg], wv[mg].x, pa);
                        fma2(acc[mg], wv[mg].y, pb);
                    }
                }
            } else {
#pragma unroll 8
                for (int kk = 0; kk < 32; kk += 2) {
                    ulonglong2 wv[4];
#pragma unroll
                    for (int mg = 0; mg < 4; mg++)
                        wv[mg] = *(const ulonglong2*)(w2p + (mg+5)*1024 + kbase + kk);
                    u64 p1a = pack2(sh1[kk*128 + b]);
                    u64 p1b = pack2(sh1[(kk+1)*128 + b]);
                    u64 p2a = pack2(sh2[kk*128 + b]);
                    u64 p2b = pack2(sh2[(kk+1)*128 + b]);
                    fma2(acc[0], wv[0].x, p1a); fma2(acc[0], wv[0].y, p1b);
#pragma unroll
                    for (int mg = 1; mg < 4; mg++) {
                        fma2(acc[mg], wv[mg].x, p2a);
                        fma2(acc[mg], wv[mg].y, p2b);
                    }
                }
            }
        }

        // ---- exchange m1r/m1z partials (pure value move, bitwise safe) ----
        __syncthreads();                   // ring now reusable as scratch
        u64* ex = (u64*)ring;
        if (tg == 0) {
            ex[(p*128 + b)*2]     = acc[3];
            ex[(p*128 + b)*2 + 1] = acc[4];
        }
        __syncthreads();

        if (tg == 0 && s < 64) {   // gate0, t = s (acc 0..2 = m0 r,z,n)
            int t = s;
            float2 vR = unpk(acc[0]), vZ = unpk(acc[1]), vN = unpk(acc[2]);
            float ghr[2]={vR.x,vR.y}, ghz[2]={vZ.x,vZ.y}, ghn[2]={vN.x,vN.y};
#pragma unroll
            for (int l = 0; l < 2; l++) {
                int j = jA + l;
                float dR = __ldg(g_D + (size_t)t*G3 + j);
                float dZ = __ldg(g_D + (size_t)t*G3 + 512 + j);
                float dN = __ldg(g_D + (size_t)t*G3 + 1024 + j);
                float gir = bi0[l][0], giz = bi0[l][1], gin = bi0[l][2];
                if (t < nn) { gir += at[l][0]+dR; giz += at[l][1]+dZ; gin += at[l][2]+dN; }
                float R = ghr[l]+bh0[l][0], Z = ghz[l]+bh0[l][1], N = ghn[l]+bh0[l][2];
                float rr = sigm(gir+R), zz = sigm(giz+Z), nl = tanhf(gin + rr*N);
                float h = (1.f - zz)*nl + zz*h1p[l];
                h1p[l] = h;
                g_h1T[(size_t)s*HB + (size_t)j*128 + b] = h;
            }
        }
        if (tg == 1 && s >= 1) {   // gate1, t = s-1 (acc0=m1n, acc1..3=m2 r,z,n)
            u64 iRu = ex[(p*128 + b)*2], iZu = ex[(p*128 + b)*2 + 1];
            float2 iR = unpk(iRu), iZ = unpk(iZu), iN = unpk(acc[0]);
            float2 hR = unpk(acc[1]), hZ = unpk(acc[2]), hN = unpk(acc[3]);
            float gi_[2][3] = {{iR.x,iZ.x,iN.x},{iR.y,iZ.y,iN.y}};
            float gh_[2][3] = {{hR.x,hZ.x,hN.x},{hR.y,hZ.y,hN.y}};
#pragma unroll
            for (int l = 0; l < 2; l++) {
                int j = jA + l;
                float gir = gi_[l][0]+bi1[l][0], giz = gi_[l][1]+bi1[l][1], gin = gi_[l][2]+bi1[l][2];
                float R = gh_[l][0]+bh1[l][0], Z = gh_[l][1]+bh1[l][1], N = gh_[l][2]+bh1[l][2];
                float rr = sigm(gir+R), zz = sigm(giz+Z), nl = tanhf(gin + rr*N);
                float h = (1.f - zz)*nl + zz*h2p[l];
                h2p[l] = h;
                g_h2T[(size_t)(s-1)*HB + (size_t)j*128 + b] = h;
            }
        }
        gridbar();
    }
}

// ---------------- fused U/V GEMM (f32x2, PQt pre-packed) -------------------
__global__ void __launch_bounds__(256, 2)
uv_k(const float* __restrict__ adj_b1)
{
    extern __shared__ float us[];
    float* hb = us;          // 2 x 4096
    float* wb = us + 8192;   // 2 x 4096

    const int tid = threadIdx.x;
    const int t   = blockIdx.x >> 3;
    const int h0  = (blockIdx.x & 7) * 128;
    const int bg  = tid & 31, hg = tid >> 5;
    const int b0  = bg * 4;
    const float* hsrc = g_h2T + (size_t)t*HB;
    const float* wsrc = g_PQt + h0;

    u64 acc[8][4] = {};

#define UV_PF(c) { \
    float* hd = hb + ((c)&1)*4096; \
    float* wd = wb + ((c)&1)*4096; \
    _Pragma("unroll") for (int i = 0; i < 4; i++) { \
        int l = tid + 256*i; int row = l >> 5, c4 = l & 31; \
        cp16(hd + l*4, hsrc + (size_t)((c)*32 + row)*128  + c4*4); \
        cp16(wd + l*4, wsrc + (size_t)((c)*32 + row)*1024 + c4*4); \
    } cp_commit(); }

    UV_PF(0); UV_PF(1);
    for (int c = 0; c < 16; c++) {
        if (c < 15) cp_wait1(); else cp_wait0();
        __syncthreads();
        const float* hh = hb + (c&1)*4096;
        const float* ww = wb + (c&1)*4096;
#pragma unroll 4
        for (int kk = 0; kk < 32; kk++) {
            u64 w[8];
#pragma unroll
            for (int pp = 0; pp < 8; pp++)
                w[pp] = *(const u64*)(ww + kk*128 + hg*16 + pp*2);
            float4 hv4 = *(const float4*)(hh + kk*128 + b0);
            u64 hv[4];
            hv[0] = pack2(hv4.x); hv[1] = pack2(hv4.y);
            hv[2] = pack2(hv4.z); hv[3] = pack2(hv4.w);
#pragma unroll
            for (int pp = 0; pp < 8; pp++)
#pragma unroll
                for (int i = 0; i < 4; i++)
                    fma2(acc[pp][i], w[pp], hv[i]);
        }
        __syncthreads();
        if (c + 2 < 16) UV_PF(c + 2);
    }

#pragma unroll
    for (int pp = 0; pp < 8; pp++) {
        int hloc = h0 + hg*16 + pp*2;
#pragma unroll
        for (int i = 0; i < 4; i++) {
            float2 v = unpk(acc[pp][i]);
            int bb = b0 + i;
            if (hloc < 512) {
                *(float2*)(g_U + ((size_t)bb*64 + t)*512 + hloc) = v;
            } else {
                v.x += adj_b1[hloc - 512];
                v.y += adj_b1[hloc - 511];
                *(float2*)(g_V + ((size_t)bb*64 + t)*512 + (hloc - 512)) = v;
            }
        }
    }
}

// ---------------- pair kernel (unchanged numerics) -------------------------
__global__ void pair_k(const float* __restrict__ W2, const float* __restrict__ b2,
                       const float* __restrict__ gu, const int* __restrict__ n_nodes,
                       float* __restrict__ out)
{
    int b    = blockIdx.x;
    int warp = (int)(blockIdx.y * 8 + (threadIdx.x >> 5));
    int lane = threadIdx.x & 31;
    int nb   = n_nodes[b];
    float* ob = out + (long)b * (MNODES * MNODES);

    float4 w2a[4], w2b[4];
#pragma unroll
    for (int q = 0; q < 4; q++) {
        w2a[q] = *(const float4*)(W2 + 4 * lane + 128 * q);
        w2b[q] = *(const float4*)(W2 + HIDDEN + 4 * lane + 128 * q);
    }
    for (int pp = warp; pp < NPAIRS; pp += 16) {
        int jn = g_jj[pp];
        if (jn >= nb) continue;
        int in = g_ii[pp];
        const float* Ui = g_U + ((long)b * MNODES + in) * HIDDEN;
        const float* Vj = g_V + ((long)b * MNODES + jn) * HIDDEN;
        float a0 = 0.f, a1 = 0.f;
#pragma unroll
        for (int q = 0; q < 4; q++) {
            float4 u = *(const float4*)(Ui + 4 * lane + 128 * q);
            float4 v = *(const float4*)(Vj + 4 * lane + 128 * q);
            float m;
            m = fmaxf(u.x + v.x, 0.f); a0 = fmaf(m, w2a[q].x, a0); a1 = fmaf(m, w2b[q].x, a1);
            m = fmaxf(u.y + v.y, 0.f); a0 = fmaf(m, w2a[q].y, a0); a1 = fmaf(m, w2b[q].y, a1);
            m = fmaxf(u.z + v.z, 0.f); a0 = fmaf(m, w2a[q].z, a0); a1 = fmaf(m, w2b[q].z, a1);
            m = fmaxf(u.w + v.w, 0.f); a0 = fmaf(m, w2a[q].w, a0); a1 = fmaf(m, w2b[q].w, a1);
        }
#pragma unroll
        for (int sft = 16; sft > 0; sft >>= 1) {
            a0 += __shfl_xor_sync(0xffffffffu, a0, sft);
            a1 += __shfl_xor_sync(0xffffffffu, a1, sft);
        }
        if (lane == 0) {
            float l0 = a0 + b2[0];
            float l1 = a1 + b2[1];
            const float* g = gu + ((long)b * NPAIRS + pp) * 2;
            float g0 = -logf(-logf(g[0] + 1e-10f) + 1e-10f);
            float g1 = -logf(-logf(g[1] + 1e-10f) + 1e-10f);
            if (l0 + g0 >= l1 + g1) {
                ob[in * MNODES + jn] = 1.f;
                ob[jn * MNODES + in] = 1.f;
            }
        }
    }
}

// ---------------- host launch sequence -------------------------------------
extern "C" void kernel_launch(void* const* d_in, const int* in_sizes, int n_in,
                              void* d_out, int out_size)
{
    const float* z       = (const float*)d_in[0];
    const int*   n_nodes = (const int*)  d_in[1];
    const float* gu      = (const float*)d_in[3];
    const float* emb     = (const float*)d_in[4];
    const float* pe      = (const float*)d_in[5];
    const float* W_pre   = (const float*)d_in[6];
    const float* b_pre   = (const float*)d_in[7];
    const float* Wih0    = (const float*)d_in[8];
    const float* Whh0    = (const float*)d_in[9];
    const float* bih0    = (const float*)d_in[10];
    const float* bhh0    = (const float*)d_in[11];
    const float* Wih1    = (const float*)d_in[12];
    const float* Whh1    = (const float*)d_in[13];
    const float* bih1    = (const float*)d_in[14];
    const float* bhh1    = (const float*)d_in[15];
    const float* node_W  = (const float*)d_in[16];
    const float* adj_W1  = (const float*)d_in[17];
    const float* adj_b1  = (const float*)d_in[18];
    const float* adj_W2  = (const float*)d_in[19];
    const float* adj_b2  = (const float*)d_in[20];
    float* out = (float*)d_out;

    float *PQt;
    cudaGetSymbolAddress((void**)&PQt, g_PQt);

    static int attr_set = 0;
    if (!attr_set) {
        cudaFuncSetAttribute(rnn_pipe, cudaFuncAttributeMaxDynamicSharedMemorySize, 204800);
        cudaFuncSetAttribute(uv_k,     cudaFuncAttributeMaxDynamicSharedMemorySize, 65536);
        attr_set = 1;
    }

    // 1-3: prolog (positions rnn_pipe as 4th launch for ncu -s capture)
    precompC_k<<<MNODES, 256>>>(pe, emb, W_pre, b_pre);
    precompzW_k<<<BATCH, 256>>>(z, W_pre);
    ATD_k<<<121, 256>>>(Wih0);

    // 4: fused pipelined recurrence (persistent, 512 threads)
    rnn_pipe<<<128, 512, 204800>>>(Whh0, Whh1, Wih1, bih0, bhh0, bih1, bhh1, n_nodes);

    // 5-6: PQt[k][h'] = P^T | Q^T
    sgemm_k<64, 64, 16, 4, 4, false, true><<<dim3(8, 8), 256>>>(
        node_W, adj_W1, PQt, nullptr, HIDDEN, HIDDEN, 2 * HIDDEN, 1024);
    sgemm_k<64, 64, 16, 4, 4, false, true><<<dim3(8, 8), 256>>>(
        node_W, adj_W1 + HIDDEN, PQt + 512, nullptr, HIDDEN, HIDDEN, 2 * HIDDEN, 1024);

    // 7: fused U/V
    uv_k<<<512, 256, 65536>>>(adj_b1);

    // 8-9: output
    zero_k<<<(BATCH * MNODES * MNODES + 255) / 256, 256>>>(out, BATCH * MNODES * MNODES);
    pair_k<<<dim3(BATCH, 2), 256>>>(adj_W2, adj_b2, gu, n_nodes, out);
}

// round 12
// speedup vs baseline: 1.0408x; 1.0408x over previous
#include <cuda_runtime.h>
#include <math.h>

#define BATCH  128
#define LATENT 256
#define HIDDEN 512
#define MNODES 64
#define NPAIRS 2016
#define G3     1536
#define HB     65536

typedef unsigned long long u64;

// ---------------- device scratch (zero-initialized at load) ----------------
__device__ __align__(16) float g_Cm [MNODES*LATENT];
__device__ __align__(16) float g_zWT[LATENT*BATCH];
__device__ __align__(16) float g_AT [G3*BATCH];        // [g][b]
__device__ __align__(16) float g_D  [MNODES*G3];       // [t][g]
__device__ __align__(16) float g_PQt[HIDDEN*1024];     // [k][h'] P|Q transposed
__device__ __align__(16) float g_h1T[MNODES*HB];       // [t][k][b]
__device__ __align__(16) float g_h2T[MNODES*HB];       // [t][k][b]
__device__ __align__(16) float g_zH [HB];              // stays all-zero
__device__ __align__(16) float g_U  [BATCH*MNODES*HIDDEN];
__device__ __align__(16) float g_V  [BATCH*MNODES*HIDDEN];
__device__ int g_ii[NPAIRS];
__device__ int g_jj[NPAIRS];
__device__ unsigned g_bar_cnt;   // monotonic ticket counter (never reset)

// ---------------- f32x2 helpers (lanes = independent IEEE fma chains) ------
__device__ __forceinline__ u64 pack2(float x){u64 r;asm("mov.b64 %0,{%1,%1};":"=l"(r):"f"(x));return r;}
__device__ __forceinline__ void fma2(u64&a,u64 b,u64 c){asm("fma.rn.f32x2 %0, %1, %2, %0;":"+l"(a):"l"(b),"l"(c));}
__device__ __forceinline__ float2 unpk(u64 v){float2 f;asm("mov.b64 {%0,%1},%2;":"=f"(f.x),"=f"(f.y):"l"(v));return f;}
__device__ __forceinline__ u64 packab(float a,float b){u64 r;asm("mov.b64 %0,{%1,%2};":"=l"(r):"f"(a),"f"(b));return r;}
__device__ __forceinline__ float sigm(float x){return 1.f/(1.f+expf(-x));}

// ---------------- ticket grid barrier (replay-safe, no reset needed) -------
__device__ __forceinline__ void gridbar()
{
    __threadfence();
    __syncthreads();
    if (threadIdx.x == 0) {
        unsigned t = atomicAdd(&g_bar_cnt, 1u);
        unsigned target = (t & ~127u) + 128u;
        while (*(volatile unsigned*)&g_bar_cnt < target) {}
        __threadfence();
    }
    __syncthreads();
}

// ---------------- cp.async (L2-only .cg — cross-SM coherent) ---------------
__device__ __forceinline__ void cp16(void* smem, const void* gmem){
    unsigned s = (unsigned)__cvta_generic_to_shared(smem);
    asm volatile("cp.async.cg.shared.global [%0], [%1], 16;" :: "r"(s), "l"(gmem) : "memory");
}
__device__ __forceinline__ void cp_commit(){ asm volatile("cp.async.commit_group;" ::: "memory"); }
__device__ __forceinline__ void cp_wait0(){ asm volatile("cp.async.wait_group 0;" ::: "memory"); }
__device__ __forceinline__ void cp_wait1(){ asm volatile("cp.async.wait_group 1;" ::: "memory"); }
__device__ __forceinline__ void cp_wait2(){ asm volatile("cp.async.wait_group 2;" ::: "memory"); }

// ---------------- generic tiled fp32 GEMM body (ascending-k chain) ---------
template<int BM, int BN, int BK, int TM, int TN, bool A_ROW, bool B_NK>
__device__ __forceinline__ void sgemm_dev(const float* __restrict__ A, const float* __restrict__ B,
                                          float* __restrict__ C, const float* __restrict__ bias,
                                          int K, int lda, int ldb, int ldc, int m0, int n0,
                                          float* sms)
{
    float* As = sms;
    float* Bs = sms + BM * BK;
    constexpr int NTH = (BM / TM) * (BN / TN);
    const int tid  = threadIdx.x;
    const int tcol = tid % (BN / TN);
    const int trow = tid / (BN / TN);
    float acc[TM][TN];
#pragma unroll
    for (int i = 0; i < TM; i++)
#pragma unroll
        for (int jx = 0; jx < TN; jx++) acc[i][jx] = 0.f;
    for (int k0 = 0; k0 < K; k0 += BK) {
#pragma unroll
        for (int idx = tid; idx < BM * BK; idx += NTH) {
            int m = idx / BK, kk = idx % BK;
            As[kk*BM + m] = A_ROW ? A[(long)(m0 + m) * lda + (k0 + kk)]
                                  : A[(long)(k0 + kk) * lda + (m0 + m)];
        }
#pragma unroll
        for (int idx = tid; idx < BK * BN; idx += NTH) {
            int kk = idx / BN, n = idx % BN;
            Bs[kk*BN + n] = B_NK ? B[(long)(n0 + n) * ldb + (k0 + kk)]
                                 : B[(long)(k0 + kk) * ldb + (n0 + n)];
        }
        __syncthreads();
#pragma unroll
        for (int kk = 0; kk < BK; kk++) {
            float a[TM], bb[TN];
#pragma unroll
            for (int i = 0; i < TM; i++) a[i] = As[kk*BM + trow * TM + i];
#pragma unroll
            for (int jx = 0; jx < TN; jx++) bb[jx] = Bs[kk*BN + tcol * TN + jx];
#pragma unroll
            for (int i = 0; i < TM; i++)
#pragma unroll
                for (int jx = 0; jx < TN; jx++)
                    acc[i][jx] = fmaf(a[i], bb[jx], acc[i][jx]);
        }
        __syncthreads();
    }
#pragma unroll
    for (int i = 0; i < TM; i++) {
        int m = m0 + trow * TM + i;
#pragma unroll
        for (int jx = 0; jx < TN; jx++) {
            int n = n0 + tcol * TN + jx;
            float v = acc[i][jx];
            if (bias) v += bias[n];
            C[(long)m * ldc + n] = v;
        }
    }
}

template<int BM, int BN, int BK, int TM, int TN, bool A_ROW, bool B_NK>
__global__ void sgemm_k(const float* __restrict__ A, const float* __restrict__ B,
                        float* __restrict__ C, const float* __restrict__ bias,
                        int K, int lda, int ldb, int ldc)
{
    __shared__ float sms[BM*BK + BK*BN];
    sgemm_dev<BM,BN,BK,TM,TN,A_ROW,B_NK>(A, B, C, bias, K, lda, ldb, ldc,
                                         blockIdx.y*BM, blockIdx.x*BN, sms);
}

// ---------------- prolog fused kernel: AT + D + pairidx --------------------
__global__ void ATD_k(const float* __restrict__ Wih0)
{
    __shared__ float sms[2048];
    int bx = blockIdx.x;
    if (bx < 96) {
        sgemm_dev<64,32,16,4,2,true,false>(Wih0, g_zWT, g_AT, nullptr,
            LATENT, LATENT, BATCH, BATCH, (bx>>2)*64, (bx&3)*32, sms);
    } else if (bx < 120) {
        sgemm_dev<64,64,16,4,4,true,true>(g_Cm, Wih0, g_D, nullptr,
            LATENT, LATENT, LATENT, G3, 0, (bx-96)*64, sms);
    } else {
        for (int p = threadIdx.x; p < NPAIRS; p += 256) {
            int i = 0, rem = p;
            while (rem >= 63 - i) { rem -= 63 - i; i++; }
            g_ii[p] = i;
            g_jj[p] = i + 1 + rem;
        }
    }
}

// ---------------- small precompute kernels ---------------------------------
__global__ void precompC_k(const float* __restrict__ pe, const float* __restrict__ emb,
                           const float* __restrict__ W_pre, const float* __restrict__ b_pre)
{
    int t = blockIdx.x, l = threadIdx.x;
    const float* w = W_pre + l * 512;
    float acc = b_pre[l];
    for (int d = 0; d < 256; d++)
        acc += pe[t * 256 + d] * w[d] + emb[t * 256 + d] * w[256 + d];
    g_Cm[t * 256 + l] = acc;
}

__global__ void precompzW_k(const float* __restrict__ z, const float* __restrict__ W_pre)
{
    int b = blockIdx.x, l = threadIdx.x;
    const float* w = W_pre + l * 512;
    float acc = 0.f;
    for (int d = 0; d < 256; d++)
        acc += z[b * 256 + d] * w[d];
    g_zWT[l * BATCH + b] = acc;
}

__global__ void zero_k(float* p, int n)
{
    int i = blockIdx.x * blockDim.x + threadIdx.x;
    if (i < n) p[i] = 0.f;
}

// ---------------- persistent pipelined 2-layer GRU (256 thr, R9 layout) ----
// 128 CTAs x 256 thr, 1 CTA/SM. CTA owns j rows bx*4..bx*4+3 for all 3 mats
// (m0=Whh0 reads h1, m1=Wih1 reads h1, m2=Whh1 reads h2). Thread: b=tid&127,
// p=tid>>7 (j-pair); 9 accumulators = 9 (mat,gate) x f32x2 over the j-pair.
// Inner loop is explicitly software-pipelined: weights/h for k+2 load while
// k's 18 fma2 execute. Every accumulator is one ascending-k fma2 chain.
__global__ void __launch_bounds__(256, 1)
rnn_pipe(const float* __restrict__ Whh0, const float* __restrict__ Whh1,
         const float* __restrict__ Wih1,
         const float* __restrict__ bih0, const float* __restrict__ bhh0,
         const float* __restrict__ bih1, const float* __restrict__ bhh1,
         const int* __restrict__ n_nodes)
{
    extern __shared__ float sm[];
    u64*   sw2  = (u64*)sm;              // 9216 u64 = 72KB
    float* ring = sm + 18432;            // 4 x 8192 floats = 128KB

    const int tid = threadIdx.x;
    const int bx  = blockIdx.x;
    const int p   = tid >> 7;            // j-pair 0/1
    const int b   = tid & 127;
    const int jA  = bx*4 + 2*p;

    // stage packed weight pairs: row = mg*2 + pr, lanes {j even, j odd}
    for (int i = tid; i < 9216; i += 256) {
        int row = i >> 9, k = i & 511;
        int mg = row >> 1, pr = row & 1;
        int m = mg / 3, g = mg % 3;
        const float* W = (m == 0) ? Whh0 : (m == 1) ? Wih1 : Whh1;
        size_t r0 = (size_t)(g*512 + bx*4 + 2*pr) * 512 + k;
        sw2[i] = packab(W[r0], W[r0 + 512]);
    }
    __syncthreads();
    const u64* w2p = sw2 + p*512;

    // per-thread constants
    float bi0[2][3], bh0[2][3], bi1[2][3], bh1[2][3], at[2][3];
#pragma unroll
    for (int l = 0; l < 2; l++) {
        int j = jA + l;
#pragma unroll
        for (int g = 0; g < 3; g++) {
            bi0[l][g] = bih0[g*512 + j]; bh0[l][g] = bhh0[g*512 + j];
            bi1[l][g] = bih1[g*512 + j]; bh1[l][g] = bhh1[g*512 + j];
            at[l][g]  = g_AT[(size_t)(g*512 + j)*128 + b];
        }
    }
    const int nn = n_nodes[b];
    float h1p[2] = {0.f, 0.f}, h2p[2] = {0.f, 0.f};

    for (int s = 0; s <= 64; s++) {
        const float* b1 = (s >= 1) ? g_h1T + (size_t)(s-1)*HB : g_zH;
        const float* b2 = (s >= 2) ? g_h2T + (size_t)(s-2)*HB : g_zH;
        u64 acc[9] = {0,0,0,0,0,0,0,0,0};

        // prefetch D for this step's gate0 (consumed ~20K cycles later)
        float dpre[2][3];
        if (s < 64) {
#pragma unroll
            for (int l = 0; l < 2; l++) {
                dpre[l][0] = __ldg(g_D + (size_t)s*G3 + jA + l);
                dpre[l][1] = __ldg(g_D + (size_t)s*G3 + 512 + jA + l);
                dpre[l][2] = __ldg(g_D + (size_t)s*G3 + 1024 + jA + l);
            }
        }

        // prime ring with chunks 0..2 (32k x 128b of h1 + h2 each)
#pragma unroll
        for (int c0 = 0; c0 < 3; c0++) {
            float* buf = ring + c0*8192;
#pragma unroll
            for (int i = 0; i < 2; i++) {
                cp16(buf + (tid + 256*i)*8,        b1 + (size_t)c0*4096 + (tid + 256*i)*8);
                cp16(buf + (tid + 256*i)*8 + 4,    b1 + (size_t)c0*4096 + (tid + 256*i)*8 + 4);
            }
#pragma unroll
            for (int i = 0; i < 2; i++) {
                cp16(buf + 4096 + (tid + 256*i)*8,     b2 + (size_t)c0*4096 + (tid + 256*i)*8);
                cp16(buf + 4096 + (tid + 256*i)*8 + 4, b2 + (size_t)c0*4096 + (tid + 256*i)*8 + 4);
            }
            cp_commit();
        }

        for (int c = 0; c < 16; c++) {
            if (c <= 13) cp_wait2(); else if (c == 14) cp_wait1(); else cp_wait0();
            __syncthreads();
            if (c + 3 < 16) {
                float* buf = ring + ((c+3)&3)*8192;
#pragma unroll
                for (int i = 0; i < 2; i++) {
                    cp16(buf + (tid + 256*i)*8,        b1 + (size_t)(c+3)*4096 + (tid + 256*i)*8);
                    cp16(buf + (tid + 256*i)*8 + 4,    b1 + (size_t)(c+3)*4096 + (tid + 256*i)*8 + 4);
                }
#pragma unroll
                for (int i = 0; i < 2; i++) {
                    cp16(buf + 4096 + (tid + 256*i)*8,     b2 + (size_t)(c+3)*4096 + (tid + 256*i)*8);
                    cp16(buf + 4096 + (tid + 256*i)*8 + 4, b2 + (size_t)(c+3)*4096 + (tid + 256*i)*8 + 4);
                }
                cp_commit();
            }
            // ---- compute 32-k chunk, software-pipelined one 2-k stage ----
            const float* sh1 = ring + (c&3)*8192;
            const float* sh2 = sh1 + 4096;
            const u64* wc = w2p + c*32;

            ulonglong2 wv[9];
#pragma unroll
            for (int mg = 0; mg < 9; mg++)
                wv[mg] = *(const ulonglong2*)(wc + mg*1024);
            u64 h1a = pack2(sh1[b]),       h1b = pack2(sh1[128 + b]);
            u64 h2a = pack2(sh2[b]),       h2b = pack2(sh2[128 + b]);

#pragma unroll
            for (int kk = 0; kk < 32; kk += 2) {
                ulonglong2 wn[9];
                u64 n1a, n1b, n2a, n2b;
                if (kk < 30) {
#pragma unroll
                    for (int mg = 0; mg < 9; mg++)
                        wn[mg] = *(const ulonglong2*)(wc + mg*1024 + kk + 2);
                    n1a = pack2(sh1[(kk+2)*128 + b]); n1b = pack2(sh1[(kk+3)*128 + b]);
                    n2a = pack2(sh2[(kk+2)*128 + b]); n2b = pack2(sh2[(kk+3)*128 + b]);
                }
#pragma unroll
                for (int mg = 0; mg < 6; mg++) { fma2(acc[mg], wv[mg].x, h1a); fma2(acc[mg], wv[mg].y, h1b); }
#pragma unroll
                for (int mg = 6; mg < 9; mg++) { fma2(acc[mg], wv[mg].x, h2a); fma2(acc[mg], wv[mg].y, h2b); }
                if (kk < 30) {
#pragma unroll
                    for (int mg = 0; mg < 9; mg++) wv[mg] = wn[mg];
                    h1a = n1a; h1b = n1b; h2a = n2a; h2b = n2b;
                }
            }
        }

        if (s < 64) {   // gate0, t = s (acc 0..2 = m0 r,z,n)
            int t = s;
            float2 vR = unpk(acc[0]), vZ = unpk(acc[1]), vN = unpk(acc[2]);
            float ghr[2]={vR.x,vR.y}, ghz[2]={vZ.x,vZ.y}, ghn[2]={vN.x,vN.y};
#pragma unroll
            for (int l = 0; l < 2; l++) {
                int j = jA + l;
                float gir = bi0[l][0], giz = bi0[l][1], gin = bi0[l][2];
                if (t < nn) { gir += at[l][0]+dpre[l][0]; giz += at[l][1]+dpre[l][1]; gin += at[l][2]+dpre[l][2]; }
                float R = ghr[l]+bh0[l][0], Z = ghz[l]+bh0[l][1], N = ghn[l]+bh0[l][2];
                float rr = sigm(gir+R), zz = sigm(giz+Z), nl = tanhf(gin + rr*N);
                float h = (1.f - zz)*nl + zz*h1p[l];
                h1p[l] = h;
                g_h1T[(size_t)s*HB + (size_t)j*128 + b] = h;
            }
        }
        if (s >= 1) {   // gate1, t = s-1 (acc3..5 = m1 r,z,n; acc6..8 = m2 r,z,n)
            float2 iR = unpk(acc[3]), iZ = unpk(acc[4]), iN = unpk(acc[5]);
            float2 hR = unpk(acc[6]), hZ = unpk(acc[7]), hN = unpk(acc[8]);
            float gi_[2][3] = {{iR.x,iZ.x,iN.x},{iR.y,iZ.y,iN.y}};
            float gh_[2][3] = {{hR.x,hZ.x,hN.x},{hR.y,hZ.y,hN.y}};
#pragma unroll
            for (int l = 0; l < 2; l++) {
                int j = jA + l;
                float gir = gi_[l][0]+bi1[l][0], giz = gi_[l][1]+bi1[l][1], gin = gi_[l][2]+bi1[l][2];
                float R = gh_[l][0]+bh1[l][0], Z = gh_[l][1]+bh1[l][1], N = gh_[l][2]+bh1[l][2];
                float rr = sigm(gir+R), zz = sigm(giz+Z), nl = tanhf(gin + rr*N);
                float h = (1.f - zz)*nl + zz*h2p[l];
                h2p[l] = h;
                g_h2T[(size_t)(s-1)*HB + (size_t)j*128 + b] = h;
            }
        }
        gridbar();
    }
}

// ---------------- fused U/V GEMM (f32x2, PQt pre-packed) -------------------
__global__ void __launch_bounds__(256, 2)
uv_k(const float* __restrict__ adj_b1)
{
    extern __shared__ float us[];
    float* hb = us;          // 2 x 4096
    float* wb = us + 8192;   // 2 x 4096

    const int tid = threadIdx.x;
    const int t   = blockIdx.x >> 3;
    const int h0  = (blockIdx.x & 7) * 128;
    const int bg  = tid & 31, hg = tid >> 5;
    const int b0  = bg * 4;
    const float* hsrc = g_h2T + (size_t)t*HB;
    const float* wsrc = g_PQt + h0;

    u64 acc[8][4] = {};

#define UV_PF(c) { \
    float* hd = hb + ((c)&1)*4096; \
    float* wd = wb + ((c)&1)*4096; \
    _Pragma("unroll") for (int i = 0; i < 4; i++) { \
        int l = tid + 256*i; int row = l >> 5, c4 = l & 31; \
        cp16(hd + l*4, hsrc + (size_t)((c)*32 + row)*128  + c4*4); \
        cp16(wd + l*4, wsrc + (size_t)((c)*32 + row)*1024 + c4*4); \
    } cp_commit(); }

    UV_PF(0); UV_PF(1);
    for (int c = 0; c < 16; c++) {
        if (c < 15) cp_wait1(); else cp_wait0();
        __syncthreads();
        const float* hh = hb + (c&1)*4096;
        const float* ww = wb + (c&1)*4096;
#pragma unroll 4
        for (int kk = 0; kk < 32; kk++) {
            u64 w[8];
#pragma unroll
            for (int pp = 0; pp < 8; pp++)
                w[pp] = *(const u64*)(ww + kk*128 + hg*16 + pp*2);
            float4 hv4 = *(const float4*)(hh + kk*128 + b0);
            u64 hv[4];
            hv[0] = pack2(hv4.x); hv[1] = pack2(hv4.y);
            hv[2] = pack2(hv4.z); hv[3] = pack2(hv4.w);
#pragma unroll
            for (int pp = 0; pp < 8; pp++)
#pragma unroll
                for (int i = 0; i < 4; i++)
                    fma2(acc[pp][i], w[pp], hv[i]);
        }
        __syncthreads();
        if (c + 2 < 16) UV_PF(c + 2);
    }

#pragma unroll
    for (int pp = 0; pp < 8; pp++) {
        int hloc = h0 + hg*16 + pp*2;
#pragma unroll
        for (int i = 0; i < 4; i++) {
            float2 v = unpk(acc[pp][i]);
            int bb = b0 + i;
            if (hloc < 512) {
                *(float2*)(g_U + ((size_t)bb*64 + t)*512 + hloc) = v;
            } else {
                v.x += adj_b1[hloc - 512];
                v.y += adj_b1[hloc - 511];
                *(float2*)(g_V + ((size_t)bb*64 + t)*512 + (hloc - 512)) = v;
            }
        }
    }
}

// ---------------- pair kernel (unchanged numerics; 2x parallelism) ---------
__global__ void pair_k(const float* __restrict__ W2, const float* __restrict__ b2,
                       const float* __restrict__ gu, const int* __restrict__ n_nodes,
                       float* __restrict__ out)
{
    int b    = blockIdx.x;
    int warp = (int)(blockIdx.y * 8 + (threadIdx.x >> 5));
    int lane = threadIdx.x & 31;
    int nb   = n_nodes[b];
    float* ob = out + (long)b * (MNODES * MNODES);

    float4 w2a[4], w2b[4];
#pragma unroll
    for (int q = 0; q < 4; q++) {
        w2a[q] = *(const float4*)(W2 + 4 * lane + 128 * q);
        w2b[q] = *(const float4*)(W2 + HIDDEN + 4 * lane + 128 * q);
    }
    for (int pp = warp; pp < NPAIRS; pp += 32) {
        int jn = g_jj[pp];
        if (jn >= nb) continue;
        int in = g_ii[pp];
        const float* Ui = g_U + ((long)b * MNODES + in) * HIDDEN;
        const float* Vj = g_V + ((long)b * MNODES + jn) * HIDDEN;
        float a0 = 0.f, a1 = 0.f;
#pragma unroll
        for (int q = 0; q < 4; q++) {
            float4 u = *(const float4*)(Ui + 4 * lane + 128 * q);
            float4 v = *(const float4*)(Vj + 4 * lane + 128 * q);
            float m;
            m = fmaxf(u.x + v.x, 0.f); a0 = fmaf(m, w2a[q].x, a0); a1 = fmaf(m, w2b[q].x, a1);
            m = fmaxf(u.y + v.y, 0.f); a0 = fmaf(m, w2a[q].y, a0); a1 = fmaf(m, w2b[q].y, a1);
            m = fmaxf(u.z + v.z, 0.f); a0 = fmaf(m, w2a[q].z, a0); a1 = fmaf(m, w2b[q].z, a1);
            m = fmaxf(u.w + v.w, 0.f); a0 = fmaf(m, w2a[q].w, a0); a1 = fmaf(m, w2b[q].w, a1);
        }
#pragma unroll
        for (int sft = 16; sft > 0; sft >>= 1) {
            a0 += __shfl_xor_sync(0xffffffffu, a0, sft);
            a1 += __shfl_xor_sync(0xffffffffu, a1, sft);
        }
        if (lane == 0) {
            float l0 = a0 + b2[0];
            float l1 = a1 + b2[1];
            const float* g = gu + ((long)b * NPAIRS + pp) * 2;
            float g0 = -logf(-logf(g[0] + 1e-10f) + 1e-10f);
            float g1 = -logf(-logf(g[1] + 1e-10f) + 1e-10f);
            if (l0 + g0 >= l1 + g1) {
                ob[in * MNODES + jn] = 1.f;
                ob[jn * MNODES + in] = 1.f;
            }
        }
    }
}

// ---------------- host launch sequence -------------------------------------
extern "C" void kernel_launch(void* const* d_in, const int* in_sizes, int n_in,
                              void* d_out, int out_size)
{
    const float* z       = (const float*)d_in[0];
    const int*   n_nodes = (const int*)  d_in[1];
    const float* gu      = (const float*)d_in[3];
    const float* emb     = (const float*)d_in[4];
    const float* pe      = (const float*)d_in[5];
    const float* W_pre   = (const float*)d_in[6];
    const float* b_pre   = (const float*)d_in[7];
    const float* Wih0    = (const float*)d_in[8];
    const float* Whh0    = (const float*)d_in[9];
    const float* bih0    = (const float*)d_in[10];
    const float* bhh0    = (const float*)d_in[11];
    const float* Wih1    = (const float*)d_in[12];
    const float* Whh1    = (const float*)d_in[13];
    const float* bih1    = (const float*)d_in[14];
    const float* bhh1    = (const float*)d_in[15];
    const float* node_W  = (const float*)d_in[16];
    const float* adj_W1  = (const float*)d_in[17];
    const float* adj_b1  = (const float*)d_in[18];
    const float* adj_W2  = (const float*)d_in[19];
    const float* adj_b2  = (const float*)d_in[20];
    float* out = (float*)d_out;

    float *PQt;
    cudaGetSymbolAddress((void**)&PQt, g_PQt);

    static int attr_set = 0;
    if (!attr_set) {
        cudaFuncSetAttribute(rnn_pipe, cudaFuncAttributeMaxDynamicSharedMemorySize, 204800);
        cudaFuncSetAttribute(uv_k,     cudaFuncAttributeMaxDynamicSharedMemorySize, 65536);
        attr_set = 1;
    }

    // 1-3: prolog (positions rnn_pipe as 4th launch for ncu -s capture)
    precompC_k<<<MNODES, 256>>>(pe, emb, W_pre, b_pre);
    precompzW_k<<<BATCH, 256>>>(z, W_pre);
    ATD_k<<<121, 256>>>(Wih0);

    // 4: fused pipelined recurrence (persistent, 256 threads)
    rnn_pipe<<<128, 256, 204800>>>(Whh0, Whh1, Wih1, bih0, bhh0, bih1, bhh1, n_nodes);

    // 5-6: PQt[k][h'] = P^T | Q^T
    sgemm_k<64, 64, 16, 4, 4, false, true><<<dim3(8, 8), 256>>>(
        node_W, adj_W1, PQt, nullptr, HIDDEN, HIDDEN, 2 * HIDDEN, 1024);
    sgemm_k<64, 64, 16, 4, 4, false, true><<<dim3(8, 8), 256>>>(
        node_W, adj_W1 + HIDDEN, PQt + 512, nullptr, HIDDEN, HIDDEN, 2 * HIDDEN, 1024);

    // 7: fused U/V
    uv_k<<<512, 256, 65536>>>(adj_b1);

    // 8-9: output
    zero_k<<<(BATCH * MNODES * MNODES + 255) / 256, 256>>>(out, BATCH * MNODES * MNODES);
    pair_k<<<dim3(BATCH, 4), 256>>>(adj_W2, adj_b2, gu, n_nodes, out);
}

// round 14
// speedup vs baseline: 1.1250x; 1.0808x over previous
#include <cuda_runtime.h>
#include <stdint.h>
#include <math.h>

#define BATCH  128
#define LATENT 256
#define HIDDEN 512
#define MNODES 64
#define NPAIRS 2016
#define G3     1536
#define HB     65536

typedef unsigned long long u64;

// ---------------- device scratch (zero-initialized at load) ----------------
__device__ __align__(16) float g_Cm [MNODES*LATENT];
__device__ __align__(16) float g_zWT[LATENT*BATCH];
__device__ __align__(16) float g_AT [G3*BATCH];        // [g][b]
__device__ __align__(16) float g_D  [MNODES*G3];       // [t][g]
__device__ __align__(16) float g_PQt[HIDDEN*1024];     // [k][h'] P|Q transposed
__device__ __align__(16) float g_h1T[MNODES*HB];       // [t][k][b]
__device__ __align__(16) float g_h2T[MNODES*HB];       // [t][k][b]
__device__ __align__(16) float g_zH [HB];              // stays all-zero
__device__ __align__(16) float g_U  [BATCH*MNODES*HIDDEN];
__device__ __align__(16) float g_V  [BATCH*MNODES*HIDDEN];
__device__ int g_ii[NPAIRS];
__device__ int g_jj[NPAIRS];
__device__ unsigned g_bar_cnt;   // monotonic ticket counter (never reset)

// ---------------- f32x2 helpers (lanes = independent IEEE fma chains) ------
__device__ __forceinline__ u64 pack2(float x){u64 r;asm("mov.b64 %0,{%1,%1};":"=l"(r):"f"(x));return r;}
__device__ __forceinline__ void fma2(u64&a,u64 b,u64 c){asm("fma.rn.f32x2 %0, %1, %2, %0;":"+l"(a):"l"(b),"l"(c));}
__device__ __forceinline__ float2 unpk(u64 v){float2 f;asm("mov.b64 {%0,%1},%2;":"=f"(f.x),"=f"(f.y):"l"(v));return f;}
__device__ __forceinline__ u64 packab(float a,float b){u64 r;asm("mov.b64 %0,{%1,%2};":"=l"(r):"f"(a),"f"(b));return r;}
__device__ __forceinline__ float sigm(float x){return 1.f/(1.f+expf(-x));}

// ---------------- ticket grid barrier (replay-safe, no reset needed) -------
__device__ __forceinline__ void gridbar()
{
    __threadfence();
    __syncthreads();
    if (threadIdx.x == 0) {
        unsigned t = atomicAdd(&g_bar_cnt, 1u);
        unsigned target = (t & ~127u) + 128u;
        while (*(volatile unsigned*)&g_bar_cnt < target) {}
        __threadfence();
    }
    __syncthreads();
}

// ---------------- cp.async.cg (16B, L2-coherent) — used by uv_k ------------
__device__ __forceinline__ void cp16(void* smem, const void* gmem){
    unsigned s = (unsigned)__cvta_generic_to_shared(smem);
    asm volatile("cp.async.cg.shared.global [%0], [%1], 16;" :: "r"(s), "l"(gmem) : "memory");
}
__device__ __forceinline__ void cp_commit(){ asm volatile("cp.async.commit_group;" ::: "memory"); }
__device__ __forceinline__ void cp_wait0(){ asm volatile("cp.async.wait_group 0;" ::: "memory"); }
__device__ __forceinline__ void cp_wait1(){ asm volatile("cp.async.wait_group 1;" ::: "memory"); }

// ---------------- TMA bulk + mbarrier (zero per-thread L1 ops) -------------
__device__ __forceinline__ void mbar_init(uint32_t a, unsigned c){
    asm volatile("mbarrier.init.shared.b64 [%0], %1;" :: "r"(a), "r"(c) : "memory");
}
__device__ __forceinline__ void mbar_arrive_tx(uint32_t a, unsigned bytes){
    asm volatile("mbarrier.arrive.expect_tx.shared.b64 _, [%0], %1;" :: "r"(a), "r"(bytes) : "memory");
}
__device__ __forceinline__ void mbar_wait(uint32_t a, unsigned ph){
    asm volatile(
        "{\n\t.reg .pred P;\n"
        "W%=:\n\t"
        "mbarrier.try_wait.parity.shared.b64 P, [%0], %1;\n\t"
        "@P bra D%=;\n\t"
        "bra W%=;\n"
        "D%=:\n\t}"
        :: "r"(a), "r"(ph) : "memory");
}
__device__ __forceinline__ void bulk_g2s(uint32_t dst, const float* src, unsigned bytes, uint32_t mb){
    asm volatile("cp.async.bulk.shared::cluster.global.mbarrier::complete_tx::bytes [%0], [%1], %2, [%3];"
                 :: "r"(dst), "l"(src), "r"(bytes), "r"(mb) : "memory");
}
__device__ __forceinline__ void fence_proxy(){ asm volatile("fence.proxy.async.shared::cta;" ::: "memory"); }

// ---------------- generic tiled fp32 GEMM body (ascending-k chain) ---------
template<int BM, int BN, int BK, int TM, int TN, bool A_ROW, bool B_NK>
__device__ __forceinline__ void sgemm_dev(const float* __restrict__ A, const float* __restrict__ B,
                                          float* __restrict__ C, const float* __restrict__ bias,
                                          int K, int lda, int ldb, int ldc, int m0, int n0,
                                          float* sms)
{
    float* As = sms;
    float* Bs = sms + BM * BK;
    constexpr int NTH = (BM / TM) * (BN / TN);
    const int tid  = threadIdx.x;
    const int tcol = tid % (BN / TN);
    const int trow = tid / (BN / TN);
    float acc[TM][TN];
#pragma unroll
    for (int i = 0; i < TM; i++)
#pragma unroll
        for (int jx = 0; jx < TN; jx++) acc[i][jx] = 0.f;
    for (int k0 = 0; k0 < K; k0 += BK) {
#pragma unroll
        for (int idx = tid; idx < BM * BK; idx += NTH) {
            int m = idx / BK, kk = idx % BK;
            As[kk*BM + m] = A_ROW ? A[(long)(m0 + m) * lda + (k0 + kk)]
                                  : A[(long)(k0 + kk) * lda + (m0 + m)];
        }
#pragma unroll
        for (int idx = tid; idx < BK * BN; idx += NTH) {
            int kk = idx / BN, n = idx % BN;
            Bs[kk*BN + n] = B_NK ? B[(long)(n0 + n) * ldb + (k0 + kk)]
                                 : B[(long)(k0 + kk) * ldb + (n0 + n)];
        }
        __syncthreads();
#pragma unroll
        for (int kk = 0; kk < BK; kk++) {
            float a[TM], bb[TN];
#pragma unroll
            for (int i = 0; i < TM; i++) a[i] = As[kk*BM + trow * TM + i];
#pragma unroll
            for (int jx = 0; jx < TN; jx++) bb[jx] = Bs[kk*BN + tcol * TN + jx];
#pragma unroll
            for (int i = 0; i < TM; i++)
#pragma unroll
                for (int jx = 0; jx < TN; jx++)
                    acc[i][jx] = fmaf(a[i], bb[jx], acc[i][jx]);
        }
        __syncthreads();
    }
#pragma unroll
    for (int i = 0; i < TM; i++) {
        int m = m0 + trow * TM + i;
#pragma unroll
        for (int jx = 0; jx < TN; jx++) {
            int n = n0 + tcol * TN + jx;
            float v = acc[i][jx];
            if (bias) v += bias[n];
            C[(long)m * ldc + n] = v;
        }
    }
}

template<int BM, int BN, int BK, int TM, int TN, bool A_ROW, bool B_NK>
__global__ void sgemm_k(const float* __restrict__ A, const float* __restrict__ B,
                        float* __restrict__ C, const float* __restrict__ bias,
                        int K, int lda, int ldb, int ldc)
{
    __shared__ float sms[BM*BK + BK*BN];
    sgemm_dev<BM,BN,BK,TM,TN,A_ROW,B_NK>(A, B, C, bias, K, lda, ldb, ldc,
                                         blockIdx.y*BM, blockIdx.x*BN, sms);
}

// ---------------- prolog fused kernel: AT + D + pairidx --------------------
__global__ void ATD_k(const float* __restrict__ Wih0)
{
    __shared__ float sms[2048];
    int bx = blockIdx.x;
    if (bx < 96) {
        sgemm_dev<64,32,16,4,2,true,false>(Wih0, g_zWT, g_AT, nullptr,
            LATENT, LATENT, BATCH, BATCH, (bx>>2)*64, (bx&3)*32, sms);
    } else if (bx < 120) {
        sgemm_dev<64,64,16,4,4,true,true>(g_Cm, Wih0, g_D, nullptr,
            LATENT, LATENT, LATENT, G3, 0, (bx-96)*64, sms);
    } else {
        for (int p = threadIdx.x; p < NPAIRS; p += 256) {
            int i = 0, rem = p;
            while (rem >= 63 - i) { rem -= 63 - i; i++; }
            g_ii[p] = i;
            g_jj[p] = i + 1 + rem;
        }
    }
}

// ---------------- small precompute kernels ---------------------------------
__global__ void precompC_k(const float* __restrict__ pe, const float* __restrict__ emb,
                           const float* __restrict__ W_pre, const float* __restrict__ b_pre)
{
    int t = blockIdx.x, l = threadIdx.x;
    const float* w = W_pre + l * 512;
    float acc = b_pre[l];
    for (int d = 0; d < 256; d++)
        acc += pe[t * 256 + d] * w[d] + emb[t * 256 + d] * w[256 + d];
    g_Cm[t * 256 + l] = acc;
}

__global__ void precompzW_k(const float* __restrict__ z, const float* __restrict__ W_pre)
{
    int b = blockIdx.x, l = threadIdx.x;
    const float* w = W_pre + l * 512;
    float acc = 0.f;
    for (int d = 0; d < 256; d++)
        acc += z[b * 256 + d] * w[d];
    g_zWT[l * BATCH + b] = acc;
}

__global__ void zero_k(float* p, int n)
{
    int i = blockIdx.x * blockDim.x + threadIdx.x;
    if (i < n) p[i] = 0.f;
}

// ---------------- persistent pipelined 2-layer GRU (TMA-staged) ------------
// 128 CTAs x 256 thr, 1 CTA/SM. CTA owns j rows bx*4..bx*4+3 for all 3 mats
// (m0=Whh0 reads h1, m1=Wih1 reads h1, m2=Whh1 reads h2). Thread: b=tid&127,
// p=tid>>7 (j-pair); 9 accumulators = 9 (mat,gate) x f32x2 over the j-pair.
// h staged via cp.async.bulk (TMA) into a 4x32KB ring with mbarriers — no
// per-thread staging ops in the L1 pipe. Every acc is one ascending-k chain.
// Smem: [0,32) mbar x4, [256B) weights 72KB, [74752B) ring 128KB = 205824B.
__global__ void __launch_bounds__(256, 1)
rnn_pipe(const float* __restrict__ Whh0, const float* __restrict__ Whh1,
         const float* __restrict__ Wih1,
         const float* __restrict__ bih0, const float* __restrict__ bhh0,
         const float* __restrict__ bih1, const float* __restrict__ bhh1,
         const int* __restrict__ n_nodes)
{
    extern __shared__ float sm[];
    u64*   sw2  = (u64*)(sm + 64);       // 9216 u64 = 72KB @ byte 256
    float* ring = sm + 18688;            // 4 x 8192 floats = 128KB @ byte 74752

    const int tid = threadIdx.x;
    const int bx  = blockIdx.x;
    const int p   = tid >> 7;            // j-pair 0/1
    const int b   = tid & 127;
    const int jA  = bx*4 + 2*p;

    const uint32_t smb    = (uint32_t)__cvta_generic_to_shared(sm);
    const uint32_t ring_b = smb + 74752u;

    if (tid == 0) {
#pragma unroll
        for (int k = 0; k < 4; k++) mbar_init(smb + k*8, 1);
        fence_proxy();
    }

    // stage packed weight pairs: row = mg*2 + pr, lanes {j even, j odd}
    for (int i = tid; i < 9216; i += 256) {
        int row = i >> 9, k = i & 511;
        int mg = row >> 1, pr = row & 1;
        int m = mg / 3, g = mg % 3;
        const float* W = (m == 0) ? Whh0 : (m == 1) ? Wih1 : Whh1;
        size_t r0 = (size_t)(g*512 + bx*4 + 2*pr) * 512 + k;
        sw2[i] = packab(W[r0], W[r0 + 512]);
    }
    __syncthreads();
    const u64* w2p = sw2 + p*512;

    // per-thread constants
    float bi0[2][3], bh0[2][3], bi1[2][3], bh1[2][3], at[2][3];
#pragma unroll
    for (int l = 0; l < 2; l++) {
        int j = jA + l;
#pragma unroll
        for (int g = 0; g < 3; g++) {
            bi0[l][g] = bih0[g*512 + j]; bh0[l][g] = bhh0[g*512 + j];
            bi1[l][g] = bih1[g*512 + j]; bh1[l][g] = bhh1[g*512 + j];
            at[l][g]  = g_AT[(size_t)(g*512 + j)*128 + b];
        }
    }
    const int nn = n_nodes[b];
    float h1p[2] = {0.f, 0.f}, h2p[2] = {0.f, 0.f};

    for (int s = 0; s <= 64; s++) {
        const float* b1 = (s >= 1) ? g_h1T + (size_t)(s-1)*HB : g_zH;
        const float* b2 = (s >= 2) ? g_h2T + (size_t)(s-2)*HB : g_zH;
        u64 acc[9] = {0,0,0,0,0,0,0,0,0};

        // prefetch D for this step's gate0 (consumed ~20K cycles later)
        float dpre[2][3];
        if (s < 64) {
#pragma unroll
            for (int l = 0; l < 2; l++) {
                dpre[l][0] = __ldg(g_D + (size_t)s*G3 + jA + l);
                dpre[l][1] = __ldg(g_D + (size_t)s*G3 + 512 + jA + l);
                dpre[l][2] = __ldg(g_D + (size_t)s*G3 + 1024 + jA + l);
            }
        }

        // prime ring slots 0..2 (16KB h1 + 16KB h2 each) via TMA bulk
        if (tid == 0) {
#pragma unroll
            for (int c0 = 0; c0 < 3; c0++) {
                uint32_t mb  = smb + c0*8u;
                uint32_t dst = ring_b + c0*32768u;
                mbar_arrive_tx(mb, 32768u);
                bulk_g2s(dst,          b1 + (size_t)c0*4096, 16384u, mb);
                bulk_g2s(dst + 16384u, b2 + (size_t)c0*4096, 16384u, mb);
            }
        }

        for (int c = 0; c < 16; c++) {
            if (tid == 0 && c + 3 < 16) {
                int cn = c + 3;
                uint32_t mb  = smb + (uint32_t)(cn & 3)*8u;
                uint32_t dst = ring_b + (uint32_t)(cn & 3)*32768u;
                mbar_arrive_tx(mb, 32768u);
                bulk_g2s(dst,          b1 + (size_t)cn*4096, 16384u, mb);
                bulk_g2s(dst + 16384u, b2 + (size_t)cn*4096, 16384u, mb);
            }
            mbar_wait(smb + (uint32_t)(c & 3)*8u, (unsigned)((s*4 + (c >> 2)) & 1));

            const float* sh1 = ring + (c & 3)*8192;
            const float* sh2 = sh1 + 4096;
            const u64* wc = w2p + c*32;
#pragma unroll 8
            for (int kk = 0; kk < 32; kk += 2) {
                ulonglong2 wv[9];
#pragma unroll
                for (int mg = 0; mg < 9; mg++)
                    wv[mg] = *(const ulonglong2*)(wc + mg*1024 + kk);
                u64 p1a = pack2(sh1[kk*128 + b]);
                u64 p1b = pack2(sh1[(kk+1)*128 + b]);
                u64 p2a = pack2(sh2[kk*128 + b]);
                u64 p2b = pack2(sh2[(kk+1)*128 + b]);
#pragma unroll
                for (int mg = 0; mg < 6; mg++) { fma2(acc[mg], wv[mg].x, p1a); fma2(acc[mg], wv[mg].y, p1b); }
#pragma unroll
                for (int mg = 6; mg < 9; mg++) { fma2(acc[mg], wv[mg].x, p2a); fma2(acc[mg], wv[mg].y, p2b); }
            }
            __syncthreads();   // slot-reuse safety: prefetch for this slot next occurs after all threads pass here
        }

        if (s < 64) {   // gate0, t = s (acc 0..2 = m0 r,z,n)
            int t = s;
            float2 vR = unpk(acc[0]), vZ = unpk(acc[1]), vN = unpk(acc[2]);
            float ghr[2]={vR.x,vR.y}, ghz[2]={vZ.x,vZ.y}, ghn[2]={vN.x,vN.y};
#pragma unroll
            for (int l = 0; l < 2; l++) {
                int j = jA + l;
                float gir = bi0[l][0], giz = bi0[l][1], gin = bi0[l][2];
                if (t < nn) { gir += at[l][0]+dpre[l][0]; giz += at[l][1]+dpre[l][1]; gin += at[l][2]+dpre[l][2]; }
                float R = ghr[l]+bh0[l][0], Z = ghz[l]+bh0[l][1], N = ghn[l]+bh0[l][2];
                float rr = sigm(gir+R), zz = sigm(giz+Z), nl = tanhf(gin + rr*N);
                float h = (1.f - zz)*nl + zz*h1p[l];
                h1p[l] = h;
                g_h1T[(size_t)s*HB + (size_t)j*128 + b] = h;
            }
        }
        if (s >= 1) {   // gate1, t = s-1 (acc3..5 = m1 r,z,n; acc6..8 = m2 r,z,n)
            float2 iR = unpk(acc[3]), iZ = unpk(acc[4]), iN = unpk(acc[5]);
            float2 hR = unpk(acc[6]), hZ = unpk(acc[7]), hN = unpk(acc[8]);
            float gi_[2][3] = {{iR.x,iZ.x,iN.x},{iR.y,iZ.y,iN.y}};
            float gh_[2][3] = {{hR.x,hZ.x,hN.x},{hR.y,hZ.y,hN.y}};
#pragma unroll
            for (int l = 0; l < 2; l++) {
                int j = jA + l;
                float gir = gi_[l][0]+bi1[l][0], giz = gi_[l][1]+bi1[l][1], gin = gi_[l][2]+bi1[l][2];
                float R = gh_[l][0]+bh1[l][0], Z = gh_[l][1]+bh1[l][1], N = gh_[l][2]+bh1[l][2];
                float rr = sigm(gir+R), zz = sigm(giz+Z), nl = tanhf(gin + rr*N);
                float h = (1.f - zz)*nl + zz*h2p[l];
                h2p[l] = h;
                g_h2T[(size_t)(s-1)*HB + (size_t)j*128 + b] = h;
            }
        }
        gridbar();
    }
}

// ---------------- fused U/V GEMM (f32x2, PQt pre-packed) -------------------
__global__ void __launch_bounds__(256, 2)
uv_k(const float* __restrict__ adj_b1)
{
    extern __shared__ float us[];
    float* hb = us;          // 2 x 4096
    float* wb = us + 8192;   // 2 x 4096

    const int tid = threadIdx.x;
    const int t   = blockIdx.x >> 3;
    const int h0  = (blockIdx.x & 7) * 128;
    const int bg  = tid & 31, hg = tid >> 5;
    const int b0  = bg * 4;
    const float* hsrc = g_h2T + (size_t)t*HB;
    const float* wsrc = g_PQt + h0;

    u64 acc[8][4] = {};

#define UV_PF(c) { \
    float* hd = hb + ((c)&1)*4096; \
    float* wd = wb + ((c)&1)*4096; \
    _Pragma("unroll") for (int i = 0; i < 4; i++) { \
        int l = tid + 256*i; int row = l >> 5, c4 = l & 31; \
        cp16(hd + l*4, hsrc + (size_t)((c)*32 + row)*128  + c4*4); \
        cp16(wd + l*4, wsrc + (size_t)((c)*32 + row)*1024 + c4*4); \
    } cp_commit(); }

    UV_PF(0); UV_PF(1);
    for (int c = 0; c < 16; c++) {
        if (c < 15) cp_wait1(); else cp_wait0();
        __syncthreads();
        const float* hh = hb + (c&1)*4096;
        const float* ww = wb + (c&1)*4096;
#pragma unroll 4
        for (int kk = 0; kk < 32; kk++) {
            u64 w[8];
#pragma unroll
            for (int pp = 0; pp < 8; pp++)
                w[pp] = *(const u64*)(ww + kk*128 + hg*16 + pp*2);
            float4 hv4 = *(const float4*)(hh + kk*128 + b0);
            u64 hv[4];
            hv[0] = pack2(hv4.x); hv[1] = pack2(hv4.y);
            hv[2] = pack2(hv4.z); hv[3] = pack2(hv4.w);
#pragma unroll
            for (int pp = 0; pp < 8; pp++)
#pragma unroll
                for (int i = 0; i < 4; i++)
                    fma2(acc[pp][i], w[pp], hv[i]);
        }
        __syncthreads();
        if (c + 2 < 16) UV_PF(c + 2);
    }

#pragma unroll
    for (int pp = 0; pp < 8; pp++) {
        int hloc = h0 + hg*16 + pp*2;
#pragma unroll
        for (int i = 0; i < 4; i++) {
            float2 v = unpk(acc[pp][i]);
            int bb = b0 + i;
            if (hloc < 512) {
                *(float2*)(g_U + ((size_t)bb*64 + t)*512 + hloc) = v;
            } else {
                v.x += adj_b1[hloc - 512];
                v.y += adj_b1[hloc - 511];
                *(float2*)(g_V + ((size_t)bb*64 + t)*512 + (hloc - 512)) = v;
            }
        }
    }
}

// ---------------- pair kernel (unchanged numerics) -------------------------
__global__ void pair_k(const float* __restrict__ W2, const float* __restrict__ b2,
                       const float* __restrict__ gu, const int* __restrict__ n_nodes,
                       float* __restrict__ out)
{
    int b    = blockIdx.x;
    int warp = (int)(blockIdx.y * 8 + (threadIdx.x >> 5));
    int lane = threadIdx.x & 31;
    int nb   = n_nodes[b];
    float* ob = out + (long)b * (MNODES * MNODES);

    float4 w2a[4], w2b[4];
#pragma unroll
    for (int q = 0; q < 4; q++) {
        w2a[q] = *(const float4*)(W2 + 4 * lane + 128 * q);
        w2b[q] = *(const float4*)(W2 + HIDDEN + 4 * lane + 128 * q);
    }
    for (int pp = warp; pp < NPAIRS; pp += 32) {
        int jn = g_jj[pp];
        if (jn >= nb) continue;
        int in = g_ii[pp];
        const float* Ui = g_U + ((long)b * MNODES + in) * HIDDEN;
        const float* Vj = g_V + ((long)b * MNODES + jn) * HIDDEN;
        float a0 = 0.f, a1 = 0.f;
#pragma unroll
        for (int q = 0; q < 4; q++) {
            float4 u = *(const float4*)(Ui + 4 * lane + 128 * q);
            float4 v = *(const float4*)(Vj + 4 * lane + 128 * q);
            float m;
            m = fmaxf(u.x + v.x, 0.f); a0 = fmaf(m, w2a[q].x, a0); a1 = fmaf(m, w2b[q].x, a1);
            m = fmaxf(u.y + v.y, 0.f); a0 = fmaf(m, w2a[q].y, a0); a1 = fmaf(m, w2b[q].y, a1);
            m = fmaxf(u.z + v.z, 0.f); a0 = fmaf(m, w2a[q].z, a0); a1 = fmaf(m, w2b[q].z, a1);
            m = fmaxf(u.w + v.w, 0.f); a0 = fmaf(m, w2a[q].w, a0); a1 = fmaf(m, w2b[q].w, a1);
        }
#pragma unroll
        for (int sft = 16; sft > 0; sft >>= 1) {
            a0 += __shfl_xor_sync(0xffffffffu, a0, sft);
            a1 += __shfl_xor_sync(0xffffffffu, a1, sft);
        }
        if (lane == 0) {
            float l0 = a0 + b2[0];
            float l1 = a1 + b2[1];
            const float* g = gu + ((long)b * NPAIRS + pp) * 2;
            float g0 = -logf(-logf(g[0] + 1e-10f) + 1e-10f);
            float g1 = -logf(-logf(g[1] + 1e-10f) + 1e-10f);
            if (l0 + g0 >= l1 + g1) {
                ob[in * MNODES + jn] = 1.f;
                ob[jn * MNODES + in] = 1.f;
            }
        }
    }
}

// ---------------- host launch sequence -------------------------------------
extern "C" void kernel_launch(void* const* d_in, const int* in_sizes, int n_in,
                              void* d_out, int out_size)
{
    const float* z       = (const float*)d_in[0];
    const int*   n_nodes = (const int*)  d_in[1];
    const float* gu      = (const float*)d_in[3];
    const float* emb     = (const float*)d_in[4];
    const float* pe      = (const float*)d_in[5];
    const float* W_pre   = (const float*)d_in[6];
    const float* b_pre   = (const float*)d_in[7];
    const float* Wih0    = (const float*)d_in[8];
    const float* Whh0    = (const float*)d_in[9];
    const float* bih0    = (const float*)d_in[10];
    const float* bhh0    = (const float*)d_in[11];
    const float* Wih1    = (const float*)d_in[12];
    const float* Whh1    = (const float*)d_in[13];
    const float* bih1    = (const float*)d_in[14];
    const float* bhh1    = (const float*)d_in[15];
    const float* node_W  = (const float*)d_in[16];
    const float* adj_W1  = (const float*)d_in[17];
    const float* adj_b1  = (const float*)d_in[18];
    const float* adj_W2  = (const float*)d_in[19];
    const float* adj_b2  = (const float*)d_in[20];
    float* out = (float*)d_out;

    float *PQt;
    cudaGetSymbolAddress((void**)&PQt, g_PQt);

    static int attr_set = 0;
    if (!attr_set) {
        cudaFuncSetAttribute(rnn_pipe, cudaFuncAttributeMaxDynamicSharedMemorySize, 205824);
        cudaFuncSetAttribute(uv_k,     cudaFuncAttributeMaxDynamicSharedMemorySize, 65536);
        attr_set = 1;
    }

    // 1-3: prolog (positions rnn_pipe as 4th launch for ncu -s capture)
    precompC_k<<<MNODES, 256>>>(pe, emb, W_pre, b_pre);
    precompzW_k<<<BATCH, 256>>>(z, W_pre);
    ATD_k<<<121, 256>>>(Wih0);

    // 4: fused pipelined recurrence (persistent, TMA-staged)
    rnn_pipe<<<128, 256, 205824>>>(Whh0, Whh1, Wih1, bih0, bhh0, bih1, bhh1, n_nodes);

    // 5-6: PQt[k][h'] = P^T | Q^T
    sgemm_k<64, 64, 16, 4, 4, false, true><<<dim3(8, 8), 256>>>(
        node_W, adj_W1, PQt, nullptr, HIDDEN, HIDDEN, 2 * HIDDEN, 1024);
    sgemm_k<64, 64, 16, 4, 4, false, true><<<dim3(8, 8), 256>>>(
        node_W, adj_W1 + HIDDEN, PQt + 512, nullptr, HIDDEN, HIDDEN, 2 * HIDDEN, 1024);

    // 7: fused U/V
    uv_k<<<512, 256, 65536>>>(adj_b1);

    // 8-9: output
    zero_k<<<(BATCH * MNODES * MNODES + 255) / 256, 256>>>(out, BATCH * MNODES * MNODES);
    pair_k<<<dim3(BATCH, 4), 256>>>(adj_W2, adj_b2, gu, n_nodes, out);
}

// round 15
// speedup vs baseline: 1.3631x; 1.2117x over previous
#include <cuda_runtime.h>
#include <stdint.h>
#include <math.h>

#define BATCH  128
#define LATENT 256
#define HIDDEN 512
#define MNODES 64
#define NPAIRS 2016
#define G3     1536
#define HB     65536

typedef unsigned long long u64;

// ---------------- device scratch (zero-initialized at load) ----------------
__device__ __align__(16) float g_Cm [MNODES*LATENT];
__device__ __align__(16) float g_zWT[LATENT*BATCH];
__device__ __align__(16) float g_AT [G3*BATCH];        // [g][b]
__device__ __align__(16) float g_D  [MNODES*G3];       // [t][g]
__device__ __align__(16) float g_PQt[HIDDEN*1024];     // [k][h'] P|Q transposed
__device__ __align__(16) float g_h1T[MNODES*HB];       // [t][k][b]
__device__ __align__(16) float g_h2T[MNODES*HB];       // [t][k][b]
__device__ __align__(16) float g_zH [HB];              // stays all-zero
__device__ __align__(16) float g_U  [BATCH*MNODES*HIDDEN];
__device__ __align__(16) float g_V  [BATCH*MNODES*HIDDEN];
__device__ int g_ii[NPAIRS];
__device__ int g_jj[NPAIRS];
__device__ unsigned g_bar_cnt;   // monotonic ticket counter (never reset)

// ---------------- f32x2 helpers (lanes = independent IEEE fma chains) ------
__device__ __forceinline__ u64 pack2(float x){u64 r;asm("mov.b64 %0,{%1,%1};":"=l"(r):"f"(x));return r;}
__device__ __forceinline__ void fma2(u64&a,u64 b,u64 c){asm("fma.rn.f32x2 %0, %1, %2, %0;":"+l"(a):"l"(b),"l"(c));}
__device__ __forceinline__ float2 unpk(u64 v){float2 f;asm("mov.b64 {%0,%1},%2;":"=f"(f.x),"=f"(f.y):"l"(v));return f;}
__device__ __forceinline__ u64 packab(float a,float b){u64 r;asm("mov.b64 %0,{%1,%2};":"=l"(r):"f"(a),"f"(b));return r;}
__device__ __forceinline__ float sigm(float x){return 1.f/(1.f+expf(-x));}

// ---------------- ticket grid barrier (replay-safe, no reset needed) -------
__device__ __forceinline__ void gridbar()
{
    __threadfence();
    __syncthreads();
    if (threadIdx.x == 0) {
        unsigned t = atomicAdd(&g_bar_cnt, 1u);
        unsigned target = (t & ~127u) + 128u;
        while (*(volatile unsigned*)&g_bar_cnt < target) {}
        __threadfence();
    }
    __syncthreads();
}

// ---------------- cp.async.cg (16B, L2-coherent) — used by uv_k ------------
__device__ __forceinline__ void cp16(void* smem, const void* gmem){
    unsigned s = (unsigned)__cvta_generic_to_shared(smem);
    asm volatile("cp.async.cg.shared.global [%0], [%1], 16;" :: "r"(s), "l"(gmem) : "memory");
}
__device__ __forceinline__ void cp_commit(){ asm volatile("cp.async.commit_group;" ::: "memory"); }
__device__ __forceinline__ void cp_wait0(){ asm volatile("cp.async.wait_group 0;" ::: "memory"); }
__device__ __forceinline__ void cp_wait1(){ asm volatile("cp.async.wait_group 1;" ::: "memory"); }

// ---------------- TMA bulk + mbarrier (zero per-thread L1 ops) -------------
__device__ __forceinline__ void mbar_init(uint32_t a, unsigned c){
    asm volatile("mbarrier.init.shared.b64 [%0], %1;" :: "r"(a), "r"(c) : "memory");
}
__device__ __forceinline__ void mbar_arrive_tx(uint32_t a, unsigned bytes){
    asm volatile("mbarrier.arrive.expect_tx.shared.b64 _, [%0], %1;" :: "r"(a), "r"(bytes) : "memory");
}
__device__ __forceinline__ void mbar_wait(uint32_t a, unsigned ph){
    asm volatile(
        "{\n\t.reg .pred P;\n"
        "W%=:\n\t"
        "mbarrier.try_wait.parity.shared.b64 P, [%0], %1;\n\t"
        "@P bra D%=;\n\t"
        "bra W%=;\n"
        "D%=:\n\t}"
        :: "r"(a), "r"(ph) : "memory");
}
__device__ __forceinline__ void bulk_g2s(uint32_t dst, const float* src, unsigned bytes, uint32_t mb){
    asm volatile("cp.async.bulk.shared::cluster.global.mbarrier::complete_tx::bytes [%0], [%1], %2, [%3];"
                 :: "r"(dst), "l"(src), "r"(bytes), "r"(mb) : "memory");
}
__device__ __forceinline__ void fence_proxy(){ asm volatile("fence.proxy.async.shared::cta;" ::: "memory"); }

// ---------------- generic tiled fp32 GEMM body (ascending-k chain) ---------
template<int BM, int BN, int BK, int TM, int TN, bool A_ROW, bool B_NK>
__device__ __forceinline__ void sgemm_dev(const float* __restrict__ A, const float* __restrict__ B,
                                          float* __restrict__ C, const float* __restrict__ bias,
                                          int K, int lda, int ldb, int ldc, int m0, int n0,
                                          float* sms)
{
    float* As = sms;
    float* Bs = sms + BM * BK;
    constexpr int NTH = (BM / TM) * (BN / TN);
    const int tid  = threadIdx.x;
    const int tcol = tid % (BN / TN);
    const int trow = tid / (BN / TN);
    float acc[TM][TN];
#pragma unroll
    for (int i = 0; i < TM; i++)
#pragma unroll
        for (int jx = 0; jx < TN; jx++) acc[i][jx] = 0.f;
    for (int k0 = 0; k0 < K; k0 += BK) {
#pragma unroll
        for (int idx = tid; idx < BM * BK; idx += NTH) {
            int m = idx / BK, kk = idx % BK;
            As[kk*BM + m] = A_ROW ? A[(long)(m0 + m) * lda + (k0 + kk)]
                                  : A[(long)(k0 + kk) * lda + (m0 + m)];
        }
#pragma unroll
        for (int idx = tid; idx < BK * BN; idx += NTH) {
            int kk = idx / BN, n = idx % BN;
            Bs[kk*BN + n] = B_NK ? B[(long)(n0 + n) * ldb + (k0 + kk)]
                                 : B[(long)(k0 + kk) * ldb + (n0 + n)];
        }
        __syncthreads();
#pragma unroll
        for (int kk = 0; kk < BK; kk++) {
            float a[TM], bb[TN];
#pragma unroll
            for (int i = 0; i < TM; i++) a[i] = As[kk*BM + trow * TM + i];
#pragma unroll
            for (int jx = 0; jx < TN; jx++) bb[jx] = Bs[kk*BN + tcol * TN + jx];
#pragma unroll
            for (int i = 0; i < TM; i++)
#pragma unroll
                for (int jx = 0; jx < TN; jx++)
                    acc[i][jx] = fmaf(a[i], bb[jx], acc[i][jx]);
        }
        __syncthreads();
    }
#pragma unroll
    for (int i = 0; i < TM; i++) {
        int m = m0 + trow * TM + i;
#pragma unroll
        for (int jx = 0; jx < TN; jx++) {
            int n = n0 + tcol * TN + jx;
            float v = acc[i][jx];
            if (bias) v += bias[n];
            C[(long)m * ldc + n] = v;
        }
    }
}

template<int BM, int BN, int BK, int TM, int TN, bool A_ROW, bool B_NK>
__global__ void sgemm_k(const float* __restrict__ A, const float* __restrict__ B,
                        float* __restrict__ C, const float* __restrict__ bias,
                        int K, int lda, int ldb, int ldc)
{
    __shared__ float sms[BM*BK + BK*BN];
    sgemm_dev<BM,BN,BK,TM,TN,A_ROW,B_NK>(A, B, C, bias, K, lda, ldb, ldc,
                                         blockIdx.y*BM, blockIdx.x*BN, sms);
}

// ---------------- prolog fused kernel: AT + D + pairidx --------------------
__global__ void ATD_k(const float* __restrict__ Wih0)
{
    __shared__ float sms[2048];
    int bx = blockIdx.x;
    if (bx < 96) {
        sgemm_dev<64,32,16,4,2,true,false>(Wih0, g_zWT, g_AT, nullptr,
            LATENT, LATENT, BATCH, BATCH, (bx>>2)*64, (bx&3)*32, sms);
    } else if (bx < 120) {
        sgemm_dev<64,64,16,4,4,true,true>(g_Cm, Wih0, g_D, nullptr,
            LATENT, LATENT, LATENT, G3, 0, (bx-96)*64, sms);
    } else {
        for (int p = threadIdx.x; p < NPAIRS; p += 256) {
            int i = 0, rem = p;
            while (rem >= 63 - i) { rem -= 63 - i; i++; }
            g_ii[p] = i;
            g_jj[p] = i + 1 + rem;
        }
    }
}

// ---------------- small precompute kernels ---------------------------------
__global__ void precompC_k(const float* __restrict__ pe, const float* __restrict__ emb,
                           const float* __restrict__ W_pre, const float* __restrict__ b_pre)
{
    int t = blockIdx.x, l = threadIdx.x;
    const float* w = W_pre + l * 512;
    float acc = b_pre[l];
    for (int d = 0; d < 256; d++)
        acc += pe[t * 256 + d] * w[d] + emb[t * 256 + d] * w[256 + d];
    g_Cm[t * 256 + l] = acc;
}

__global__ void precompzW_k(const float* __restrict__ z, const float* __restrict__ W_pre)
{
    int b = blockIdx.x, l = threadIdx.x;
    const float* w = W_pre + l * 512;
    float acc = 0.f;
    for (int d = 0; d < 256; d++)
        acc += z[b * 256 + d] * w[d];
    g_zWT[l * BATCH + b] = acc;
}

__global__ void zero_k(float* p, int n)
{
    int i = blockIdx.x * blockDim.x + threadIdx.x;
    if (i < n) p[i] = 0.f;
}

// ---------------- persistent pipelined 2-layer GRU (mat-split groups) ------
// 128 CTAs x 384 thr, 1 CTA/SM. CTA owns j rows bx*4..bx*4+3 for all 3 mats.
// Thread: grp = tid/128 (mat: 0=Whh0/h1, 1=Wih1/h1, 2=Whh1/h2);
//         r = tid%128, p = r>>6 (j-pair), q = r&63, b0 = 2q (2 batch elems).
// Each thread: 3 gates x 2 b accumulators (lanes = 2 j rows). Each warp loads
// only ITS mat's 3 weight pairs (LDS.128 broadcast) + its h stream (LDS.64).
// h staged via TMA bulk ring (4x32KB) with mbarriers. Every accumulator is a
// full ascending-k fma2 chain (bitwise = R13); m1 group hands gi1 partials to
// m2 group via smem (pure value move) for the gate1 epilogue.
__global__ void __launch_bounds__(384, 1)
rnn_pipe(const float* __restrict__ Whh0, const float* __restrict__ Whh1,
         const float* __restrict__ Wih1,
         const float* __restrict__ bih0, const float* __restrict__ bhh0,
         const float* __restrict__ bih1, const float* __restrict__ bhh1,
         const int* __restrict__ n_nodes)
{
    extern __shared__ float sm[];
    u64*   sw2  = (u64*)(sm + 64);       // 9216 u64 = 72KB @ byte 256
    float* ring = sm + 18688;            // 4 x 8192 floats = 128KB @ byte 74752

    const int tid = threadIdx.x;
    const int bx  = blockIdx.x;
    const int grp = tid / 128;           // mat group 0/1/2
    const int r   = tid % 128;
    const int p   = r >> 6;              // j-pair 0/1
    const int q   = r & 63;
    const int b0  = q * 2;
    const int jA  = bx*4 + 2*p;

    const uint32_t smb    = (uint32_t)__cvta_generic_to_shared(sm);
    const uint32_t ring_b = smb + 74752u;

    if (tid == 0) {
#pragma unroll
        for (int k = 0; k < 4; k++) mbar_init(smb + k*8, 1);
        fence_proxy();
    }

    // stage packed weight pairs: row = (m*3+g)*2 + pr, lanes {j even, j odd}
    for (int i = tid; i < 9216; i += 384) {
        int row = i >> 9, k = i & 511;
        int mg = row >> 1, pr = row & 1;
        int m = mg / 3, g = mg % 3;
        const float* W = (m == 0) ? Whh0 : (m == 1) ? Wih1 : Whh1;
        size_t r0 = (size_t)(g*512 + bx*4 + 2*pr) * 512 + k;
        sw2[i] = packab(W[r0], W[r0 + 512]);
    }
    __syncthreads();

    // this thread's 3 weight-row pointers (its mat, 3 gates, its j-pair)
    const u64* wg[3];
#pragma unroll
    for (int gg = 0; gg < 3; gg++)
        wg[gg] = sw2 + (size_t)((grp*3 + gg)*2 + p)*512;

    // per-thread constants (by group)
    float bi0[2][3], bh0[2][3], bi1[2][3], bh1[2][3], at_[2][3][2];
    int2 nn2 = make_int2(0, 0);
    if (grp == 0) {
        nn2 = *(const int2*)(n_nodes + b0);
#pragma unroll
        for (int l = 0; l < 2; l++) {
            int j = jA + l;
#pragma unroll
            for (int gg = 0; gg < 3; gg++) {
                bi0[l][gg] = bih0[gg*512 + j]; bh0[l][gg] = bhh0[gg*512 + j];
                float2 a2 = *(const float2*)(g_AT + (size_t)(gg*512 + j)*128 + b0);
                at_[l][gg][0] = a2.x; at_[l][gg][1] = a2.y;
            }
        }
    } else if (grp == 2) {
#pragma unroll
        for (int l = 0; l < 2; l++) {
            int j = jA + l;
#pragma unroll
            for (int gg = 0; gg < 3; gg++) {
                bi1[l][gg] = bih1[gg*512 + j]; bh1[l][gg] = bhh1[gg*512 + j];
            }
        }
    }
    float h1p[2][2] = {{0.f,0.f},{0.f,0.f}};   // [l][i] (grp0)
    float h2p[2][2] = {{0.f,0.f},{0.f,0.f}};   // [l][i] (grp2)

    for (int s = 0; s <= 64; s++) {
        const float* b1 = (s >= 1) ? g_h1T + (size_t)(s-1)*HB : g_zH;
        const float* b2 = (s >= 2) ? g_h2T + (size_t)(s-2)*HB : g_zH;
        u64 acc[3][2] = {{0,0},{0,0},{0,0}};   // [gate][b-index]

        // prefetch D for gate0 (grp0 only; consumed ~20K cycles later)
        float dpre[2][3];
        if (grp == 0 && s < 64) {
#pragma unroll
            for (int l = 0; l < 2; l++) {
                dpre[l][0] = __ldg(g_D + (size_t)s*G3 + jA + l);
                dpre[l][1] = __ldg(g_D + (size_t)s*G3 + 512 + jA + l);
                dpre[l][2] = __ldg(g_D + (size_t)s*G3 + 1024 + jA + l);
            }
        }

        // prime ring slots 0..2 (16KB h1 + 16KB h2 each) via TMA bulk
        if (tid == 0) {
#pragma unroll
            for (int c0 = 0; c0 < 3; c0++) {
                uint32_t mb  = smb + c0*8u;
                uint32_t dst = ring_b + c0*32768u;
                mbar_arrive_tx(mb, 32768u);
                bulk_g2s(dst,          b1 + (size_t)c0*4096, 16384u, mb);
                bulk_g2s(dst + 16384u, b2 + (size_t)c0*4096, 16384u, mb);
            }
        }

        for (int c = 0; c < 16; c++) {
            if (tid == 0 && c + 3 < 16) {
                int cn = c + 3;
                uint32_t mb  = smb + (uint32_t)(cn & 3)*8u;
                uint32_t dst = ring_b + (uint32_t)(cn & 3)*32768u;
                mbar_arrive_tx(mb, 32768u);
                bulk_g2s(dst,          b1 + (size_t)cn*4096, 16384u, mb);
                bulk_g2s(dst + 16384u, b2 + (size_t)cn*4096, 16384u, mb);
            }
            mbar_wait(smb + (uint32_t)(c & 3)*8u, (unsigned)((s*4 + (c >> 2)) & 1));

            const float* slot = ring + (c & 3)*8192;
            const float* hs = (grp == 2) ? slot + 4096 : slot;   // h1 or h2
            const u64* w0 = wg[0] + c*32;
            const u64* w1 = wg[1] + c*32;
            const u64* w2 = wg[2] + c*32;
#pragma unroll 8
            for (int kk = 0; kk < 32; kk += 2) {
                ulonglong2 wv0 = *(const ulonglong2*)(w0 + kk);
                ulonglong2 wv1 = *(const ulonglong2*)(w1 + kk);
                ulonglong2 wv2 = *(const ulonglong2*)(w2 + kk);
                u64 hp0 = *(const u64*)(hs + kk*128 + b0);
                u64 hp1 = *(const u64*)(hs + (kk+1)*128 + b0);
                float2 h0f = unpk(hp0), h1f = unpk(hp1);
                u64 a0 = pack2(h0f.x), b0v = pack2(h0f.y);
                u64 a1 = pack2(h1f.x), b1v = pack2(h1f.y);
                fma2(acc[0][0], wv0.x, a0);  fma2(acc[0][0], wv0.y, a1);
                fma2(acc[1][0], wv1.x, a0);  fma2(acc[1][0], wv1.y, a1);
                fma2(acc[2][0], wv2.x, a0);  fma2(acc[2][0], wv2.y, a1);
                fma2(acc[0][1], wv0.x, b0v); fma2(acc[0][1], wv0.y, b1v);
                fma2(acc[1][1], wv1.x, b0v); fma2(acc[1][1], wv1.y, b1v);
                fma2(acc[2][1], wv2.x, b0v); fma2(acc[2][1], wv2.y, b1v);
            }
            __syncthreads();   // slot-reuse safety
        }

        // ---- m1 group hands gi1 partials to m2 group (pure value move) ----
        u64* ex = (u64*)ring;           // ring idle until next-step prime
        if (grp == 1) {
#pragma unroll
            for (int gg = 0; gg < 3; gg++) {
                ex[(r*3 + gg)*2]     = acc[gg][0];
                ex[(r*3 + gg)*2 + 1] = acc[gg][1];
            }
        }
        __syncthreads();

        if (grp == 0 && s < 64) {   // gate0, t = s
            int t = s;
            float2 vR0 = unpk(acc[0][0]), vR1 = unpk(acc[0][1]);
            float2 vZ0 = unpk(acc[1][0]), vZ1 = unpk(acc[1][1]);
            float2 vN0 = unpk(acc[2][0]), vN1 = unpk(acc[2][1]);
            float ghr[2][2] = {{vR0.x,vR1.x},{vR0.y,vR1.y}};   // [l][i]
            float ghz[2][2] = {{vZ0.x,vZ1.x},{vZ0.y,vZ1.y}};
            float ghn[2][2] = {{vN0.x,vN1.x},{vN0.y,vN1.y}};
            int nnv[2] = {nn2.x, nn2.y};
#pragma unroll
            for (int l = 0; l < 2; l++) {
                int j = jA + l;
                float hv[2];
#pragma unroll
                for (int i = 0; i < 2; i++) {
                    float gir = bi0[l][0], giz = bi0[l][1], gin = bi0[l][2];
                    if (t < nnv[i]) {
                        gir += at_[l][0][i] + dpre[l][0];
                        giz += at_[l][1][i] + dpre[l][1];
                        gin += at_[l][2][i] + dpre[l][2];
                    }
                    float R = ghr[l][i]+bh0[l][0], Z = ghz[l][i]+bh0[l][1], N = ghn[l][i]+bh0[l][2];
                    float rr = sigm(gir+R), zz = sigm(giz+Z), nl = tanhf(gin + rr*N);
                    float h = (1.f - zz)*nl + zz*h1p[l][i];
                    h1p[l][i] = h; hv[i] = h;
                }
                *(float2*)(g_h1T + (size_t)s*HB + (size_t)j*128 + b0) = make_float2(hv[0], hv[1]);
            }
        }
        if (grp == 2 && s >= 1) {   // gate1, t = s-1
            u64 giu[3][2];
#pragma unroll
            for (int gg = 0; gg < 3; gg++) {
                giu[gg][0] = ex[(r*3 + gg)*2];
                giu[gg][1] = ex[(r*3 + gg)*2 + 1];
            }
            float2 iR0 = unpk(giu[0][0]), iR1 = unpk(giu[0][1]);
            float2 iZ0 = unpk(giu[1][0]), iZ1 = unpk(giu[1][1]);
            float2 iN0 = unpk(giu[2][0]), iN1 = unpk(giu[2][1]);
            float2 hR0 = unpk(acc[0][0]), hR1 = unpk(acc[0][1]);
            float2 hZ0 = unpk(acc[1][0]), hZ1 = unpk(acc[1][1]);
            float2 hN0 = unpk(acc[2][0]), hN1 = unpk(acc[2][1]);
            float giR[2][2] = {{iR0.x,iR1.x},{iR0.y,iR1.y}};
            float giZ[2][2] = {{iZ0.x,iZ1.x},{iZ0.y,iZ1.y}};
            float giN[2][2] = {{iN0.x,iN1.x},{iN0.y,iN1.y}};
            float ghR[2][2] = {{hR0.x,hR1.x},{hR0.y,hR1.y}};
            float ghZ[2][2] = {{hZ0.x,hZ1.x},{hZ0.y,hZ1.y}};
            float ghN[2][2] = {{hN0.x,hN1.x},{hN0.y,hN1.y}};
#pragma unroll
            for (int l = 0; l < 2; l++) {
                int j = jA + l;
                float hv[2];
#pragma unroll
                for (int i = 0; i < 2; i++) {
                    float gir = giR[l][i]+bi1[l][0], giz = giZ[l][i]+bi1[l][1], gin = giN[l][i]+bi1[l][2];
                    float R = ghR[l][i]+bh1[l][0], Z = ghZ[l][i]+bh1[l][1], N = ghN[l][i]+bh1[l][2];
                    float rr = sigm(gir+R), zz = sigm(giz+Z), nl = tanhf(gin + rr*N);
                    float h = (1.f - zz)*nl + zz*h2p[l][i];
                    h2p[l][i] = h; hv[i] = h;
                }
                *(float2*)(g_h2T + (size_t)(s-1)*HB + (size_t)j*128 + b0) = make_float2(hv[0], hv[1]);
            }
        }
        gridbar();
    }
}

// ---------------- fused U/V GEMM (f32x2, PQt pre-packed) -------------------
__global__ void __launch_bounds__(256, 2)
uv_k(const float* __restrict__ adj_b1)
{
    extern __shared__ float us[];
    float* hb = us;          // 2 x 4096
    float* wb = us + 8192;   // 2 x 4096

    const int tid = threadIdx.x;
    const int t   = blockIdx.x >> 3;
    const int h0  = (blockIdx.x & 7) * 128;
    const int bg  = tid & 31, hg = tid >> 5;
    const int b0  = bg * 4;
    const float* hsrc = g_h2T + (size_t)t*HB;
    const float* wsrc = g_PQt + h0;

    u64 acc[8][4] = {};

#define UV_PF(c) { \
    float* hd = hb + ((c)&1)*4096; \
    float* wd = wb + ((c)&1)*4096; \
    _Pragma("unroll") for (int i = 0; i < 4; i++) { \
        int l = tid + 256*i; int row = l >> 5, c4 = l & 31; \
        cp16(hd + l*4, hsrc + (size_t)((c)*32 + row)*128  + c4*4); \
        cp16(wd + l*4, wsrc + (size_t)((c)*32 + row)*1024 + c4*4); \
    } cp_commit(); }

    UV_PF(0); UV_PF(1);
    for (int c = 0; c < 16; c++) {
        if (c < 15) cp_wait1(); else cp_wait0();
        __syncthreads();
        const float* hh = hb + (c&1)*4096;
        const float* ww = wb + (c&1)*4096;
#pragma unroll 4
        for (int kk = 0; kk < 32; kk++) {
            u64 w[8];
#pragma unroll
            for (int pp = 0; pp < 8; pp++)
                w[pp] = *(const u64*)(ww + kk*128 + hg*16 + pp*2);
            float4 hv4 = *(const float4*)(hh + kk*128 + b0);
            u64 hv[4];
            hv[0] = pack2(hv4.x); hv[1] = pack2(hv4.y);
            hv[2] = pack2(hv4.z); hv[3] = pack2(hv4.w);
#pragma unroll
            for (int pp = 0; pp < 8; pp++)
#pragma unroll
                for (int i = 0; i < 4; i++)
                    fma2(acc[pp][i], w[pp], hv[i]);
        }
        __syncthreads();
        if (c + 2 < 16) UV_PF(c + 2);
    }

#pragma unroll
    for (int pp = 0; pp < 8; pp++) {
        int hloc = h0 + hg*16 + pp*2;
#pragma unroll
        for (int i = 0; i < 4; i++) {
            float2 v = unpk(acc[pp][i]);
            int bb = b0 + i;
            if (hloc < 512) {
                *(float2*)(g_U + ((size_t)bb*64 + t)*512 + hloc) = v;
            } else {
                v.x += adj_b1[hloc - 512];
                v.y += adj_b1[hloc - 511];
                *(float2*)(g_V + ((size_t)bb*64 + t)*512 + (hloc - 512)) = v;
            }
        }
    }
}

// ---------------- pair kernel (unchanged numerics) -------------------------
__global__ void pair_k(const float* __restrict__ W2, const float* __restrict__ b2,
                       const float* __restrict__ gu, const int* __restrict__ n_nodes,
                       float* __restrict__ out)
{
    int b    = blockIdx.x;
    int warp = (int)(blockIdx.y * 8 + (threadIdx.x >> 5));
    int lane = threadIdx.x & 31;
    int nb   = n_nodes[b];
    float* ob = out + (long)b * (MNODES * MNODES);

    float4 w2a[4], w2b[4];
#pragma unroll
    for (int q = 0; q < 4; q++) {
        w2a[q] = *(const float4*)(W2 + 4 * lane + 128 * q);
        w2b[q] = *(const float4*)(W2 + HIDDEN + 4 * lane + 128 * q);
    }
    for (int pp = warp; pp < NPAIRS; pp += 32) {
        int jn = g_jj[pp];
        if (jn >= nb) continue;
        int in = g_ii[pp];
        const float* Ui = g_U + ((long)b * MNODES + in) * HIDDEN;
        const float* Vj = g_V + ((long)b * MNODES + jn) * HIDDEN;
        float a0 = 0.f, a1 = 0.f;
#pragma unroll
        for (int q = 0; q < 4; q++) {
            float4 u = *(const float4*)(Ui + 4 * lane + 128 * q);
            float4 v = *(const float4*)(Vj + 4 * lane + 128 * q);
            float m;
            m = fmaxf(u.x + v.x, 0.f); a0 = fmaf(m, w2a[q].x, a0); a1 = fmaf(m, w2b[q].x, a1);
            m = fmaxf(u.y + v.y, 0.f); a0 = fmaf(m, w2a[q].y, a0); a1 = fmaf(m, w2b[q].y, a1);
            m = fmaxf(u.z + v.z, 0.f); a0 = fmaf(m, w2a[q].z, a0); a1 = fmaf(m, w2b[q].z, a1);
            m = fmaxf(u.w + v.w, 0.f); a0 = fmaf(m, w2a[q].w, a0); a1 = fmaf(m, w2b[q].w, a1);
        }
#pragma unroll
        for (int sft = 16; sft > 0; sft >>= 1) {
            a0 += __shfl_xor_sync(0xffffffffu, a0, sft);
            a1 += __shfl_xor_sync(0xffffffffu, a1, sft);
        }
        if (lane == 0) {
            float l0 = a0 + b2[0];
            float l1 = a1 + b2[1];
            const float* g = gu + ((long)b * NPAIRS + pp) * 2;
            float g0 = -logf(-logf(g[0] + 1e-10f) + 1e-10f);
            float g1 = -logf(-logf(g[1] + 1e-10f) + 1e-10f);
            if (l0 + g0 >= l1 + g1) {
                ob[in * MNODES + jn] = 1.f;
                ob[jn * MNODES + in] = 1.f;
            }
        }
    }
}

// ---------------- host launch sequence -------------------------------------
extern "C" void kernel_launch(void* const* d_in, const int* in_sizes, int n_in,
                              void* d_out, int out_size)
{
    const float* z       = (const float*)d_in[0];
    const int*   n_nodes = (const int*)  d_in[1];
    const float* gu      = (const float*)d_in[3];
    const float* emb     = (const float*)d_in[4];
    const float* pe      = (const float*)d_in[5];
    const float* W_pre   = (const float*)d_in[6];
    const float* b_pre   = (const float*)d_in[7];
    const float* Wih0    = (const float*)d_in[8];
    const float* Whh0    = (const float*)d_in[9];
    const float* bih0    = (const float*)d_in[10];
    const float* bhh0    = (const float*)d_in[11];
    const float* Wih1    = (const float*)d_in[12];
    const float* Whh1    = (const float*)d_in[13];
    const float* bih1    = (const float*)d_in[14];
    const float* bhh1    = (const float*)d_in[15];
    const float* node_W  = (const float*)d_in[16];
    const float* adj_W1  = (const float*)d_in[17];
    const float* adj_b1  = (const float*)d_in[18];
    const float* adj_W2  = (const float*)d_in[19];
    const float* adj_b2  = (const float*)d_in[20];
    float* out = (float*)d_out;

    float *PQt;
    cudaGetSymbolAddress((void**)&PQt, g_PQt);

    static int attr_set = 0;
    if (!attr_set) {
        cudaFuncSetAttribute(rnn_pipe, cudaFuncAttributeMaxDynamicSharedMemorySize, 205824);
        cudaFuncSetAttribute(uv_k,     cudaFuncAttributeMaxDynamicSharedMemorySize, 65536);
        attr_set = 1;
    }

    // 1-3: prolog (positions rnn_pipe as 4th launch for ncu -s capture)
    precompC_k<<<MNODES, 256>>>(pe, emb, W_pre, b_pre);
    precompzW_k<<<BATCH, 256>>>(z, W_pre);
    ATD_k<<<121, 256>>>(Wih0);

    // 4: fused pipelined recurrence (persistent, TMA-staged, mat-split)
    rnn_pipe<<<128, 384, 205824>>>(Whh0, Whh1, Wih1, bih0, bhh0, bih1, bhh1, n_nodes);

    // 5-6: PQt[k][h'] = P^T | Q^T
    sgemm_k<64, 64, 16, 4, 4, false, true><<<dim3(8, 8), 256>>>(
        node_W, adj_W1, PQt, nullptr, HIDDEN, HIDDEN, 2 * HIDDEN, 1024);
    sgemm_k<64, 64, 16, 4, 4, false, true><<<dim3(8, 8), 256>>>(
        node_W, adj_W1 + HIDDEN, PQt + 512, nullptr, HIDDEN, HIDDEN, 2 * HIDDEN, 1024);

    // 7: fused U/V
    uv_k<<<512, 256, 65536>>>(adj_b1);

    // 8-9: output
    zero_k<<<(BATCH * MNODES * MNODES + 255) / 256, 256>>>(out, BATCH * MNODES * MNODES);
    pair_k<<<dim3(BATCH, 4), 256>>>(adj_W2, adj_b2, gu, n_nodes, out);
}

// round 16
// speedup vs baseline: 1.4122x; 1.0360x over previous
#include <cuda_runtime.h>
#include <stdint.h>
#include <math.h>

#define BATCH  128
#define LATENT 256
#define HIDDEN 512
#define MNODES 64
#define NPAIRS 2016
#define G3     1536
#define HB     65536

typedef unsigned long long u64;

// ---------------- device scratch (zero-initialized at load) ----------------
__device__ __align__(16) float g_Cm [MNODES*LATENT];
__device__ __align__(16) float g_zWT[LATENT*BATCH];
__device__ __align__(16) float g_AT [G3*BATCH];        // [g][b]
__device__ __align__(16) float g_D  [MNODES*G3];       // [t][g]
__device__ __align__(16) float g_PQt[HIDDEN*1024];     // [k][h'] P|Q transposed
__device__ __align__(16) float g_h1T[MNODES*HB];       // [t][k][b]
__device__ __align__(16) float g_h2T[MNODES*HB];       // [t][k][b]
__device__ __align__(16) float g_zH [HB];              // stays all-zero
__device__ __align__(16) float g_U  [BATCH*MNODES*HIDDEN];
__device__ __align__(16) float g_V  [BATCH*MNODES*HIDDEN];
__device__ int g_ii[NPAIRS];
__device__ int g_jj[NPAIRS];
__device__ unsigned g_bar_cnt;   // monotonic ticket counter (never reset)

// ---------------- f32x2 helpers (lanes = independent IEEE fma chains) ------
__device__ __forceinline__ u64 pack2(float x){u64 r;asm("mov.b64 %0,{%1,%1};":"=l"(r):"f"(x));return r;}
__device__ __forceinline__ void fma2(u64&a,u64 b,u64 c){asm("fma.rn.f32x2 %0, %1, %2, %0;":"+l"(a):"l"(b),"l"(c));}
__device__ __forceinline__ float2 unpk(u64 v){float2 f;asm("mov.b64 {%0,%1},%2;":"=f"(f.x),"=f"(f.y):"l"(v));return f;}
__device__ __forceinline__ u64 packab(float a,float b){u64 r;asm("mov.b64 %0,{%1,%2};":"=l"(r):"f"(a),"f"(b));return r;}
__device__ __forceinline__ float sigm(float x){return 1.f/(1.f+expf(-x));}
__device__ __forceinline__ u64 ldcg64(const float* p){
    u64 v; asm volatile("ld.global.cg.b64 %0, [%1];" : "=l"(v) : "l"(p)); return v;
}

// ---------------- ticket grid barrier (replay-safe, no reset needed) -------
__device__ __forceinline__ void gridbar()
{
    __threadfence();
    __syncthreads();
    if (threadIdx.x == 0) {
        unsigned t = atomicAdd(&g_bar_cnt, 1u);
        unsigned target = (t & ~127u) + 128u;
        while (*(volatile unsigned*)&g_bar_cnt < target) __nanosleep(32);
        __threadfence();
    }
    __syncthreads();
}

// ---------------- cp.async.cg (16B, L2-coherent) — used by uv_k ------------
__device__ __forceinline__ void cp16(void* smem, const void* gmem){
    unsigned s = (unsigned)__cvta_generic_to_shared(smem);
    asm volatile("cp.async.cg.shared.global [%0], [%1], 16;" :: "r"(s), "l"(gmem) : "memory");
}
__device__ __forceinline__ void cp_commit(){ asm volatile("cp.async.commit_group;" ::: "memory"); }
__device__ __forceinline__ void cp_wait0(){ asm volatile("cp.async.wait_group 0;" ::: "memory"); }
__device__ __forceinline__ void cp_wait1(){ asm volatile("cp.async.wait_group 1;" ::: "memory"); }

// ---------------- generic tiled fp32 GEMM body (ascending-k chain) ---------
template<int BM, int BN, int BK, int TM, int TN, bool A_ROW, bool B_NK>
__device__ __forceinline__ void sgemm_dev(const float* __restrict__ A, const float* __restrict__ B,
                                          float* __restrict__ C, const float* __restrict__ bias,
                                          int K, int lda, int ldb, int ldc, int m0, int n0,
                                          float* sms)
{
    float* As = sms;
    float* Bs = sms + BM * BK;
    constexpr int NTH = (BM / TM) * (BN / TN);
    const int tid  = threadIdx.x;
    const int tcol = tid % (BN / TN);
    const int trow = tid / (BN / TN);
    float acc[TM][TN];
#pragma unroll
    for (int i = 0; i < TM; i++)
#pragma unroll
        for (int jx = 0; jx < TN; jx++) acc[i][jx] = 0.f;
    for (int k0 = 0; k0 < K; k0 += BK) {
#pragma unroll
        for (int idx = tid; idx < BM * BK; idx += NTH) {
            int m = idx / BK, kk = idx % BK;
            As[kk*BM + m] = A_ROW ? A[(long)(m0 + m) * lda + (k0 + kk)]
                                  : A[(long)(k0 + kk) * lda + (m0 + m)];
        }
#pragma unroll
        for (int idx = tid; idx < BK * BN; idx += NTH) {
            int kk = idx / BN, n = idx % BN;
            Bs[kk*BN + n] = B_NK ? B[(long)(n0 + n) * ldb + (k0 + kk)]
                                 : B[(long)(k0 + kk) * ldb + (n0 + n)];
        }
        __syncthreads();
#pragma unroll
        for (int kk = 0; kk < BK; kk++) {
            float a[TM], bb[TN];
#pragma unroll
            for (int i = 0; i < TM; i++) a[i] = As[kk*BM + trow * TM + i];
#pragma unroll
            for (int jx = 0; jx < TN; jx++) bb[jx] = Bs[kk*BN + tcol * TN + jx];
#pragma unroll
            for (int i = 0; i < TM; i++)
#pragma unroll
                for (int jx = 0; jx < TN; jx++)
                    acc[i][jx] = fmaf(a[i], bb[jx], acc[i][jx]);
        }
        __syncthreads();
    }
#pragma unroll
    for (int i = 0; i < TM; i++) {
        int m = m0 + trow * TM + i;
#pragma unroll
        for (int jx = 0; jx < TN; jx++) {
            int n = n0 + tcol * TN + jx;
            float v = acc[i][jx];
            if (bias) v += bias[n];
            C[(long)m * ldc + n] = v;
        }
    }
}

template<int BM, int BN, int BK, int TM, int TN, bool A_ROW, bool B_NK>
__global__ void sgemm_k(const float* __restrict__ A, const float* __restrict__ B,
                        float* __restrict__ C, const float* __restrict__ bias,
                        int K, int lda, int ldb, int ldc)
{
    __shared__ float sms[BM*BK + BK*BN];
    sgemm_dev<BM,BN,BK,TM,TN,A_ROW,B_NK>(A, B, C, bias, K, lda, ldb, ldc,
                                         blockIdx.y*BM, blockIdx.x*BN, sms);
}

// ---------------- prolog fused kernel: AT + D + pairidx --------------------
__global__ void ATD_k(const float* __restrict__ Wih0)
{
    __shared__ float sms[2048];
    int bx = blockIdx.x;
    if (bx < 96) {
        sgemm_dev<64,32,16,4,2,true,false>(Wih0, g_zWT, g_AT, nullptr,
            LATENT, LATENT, BATCH, BATCH, (bx>>2)*64, (bx&3)*32, sms);
    } else if (bx < 120) {
        sgemm_dev<64,64,16,4,4,true,true>(g_Cm, Wih0, g_D, nullptr,
            LATENT, LATENT, LATENT, G3, 0, (bx-96)*64, sms);
    } else {
        for (int p = threadIdx.x; p < NPAIRS; p += 256) {
            int i = 0, rem = p;
            while (rem >= 63 - i) { rem -= 63 - i; i++; }
            g_ii[p] = i;
            g_jj[p] = i + 1 + rem;
        }
    }
}

// ---------------- small precompute kernels ---------------------------------
__global__ void precompC_k(const float* __restrict__ pe, const float* __restrict__ emb,
                           const float* __restrict__ W_pre, const float* __restrict__ b_pre)
{
    int t = blockIdx.x, l = threadIdx.x;
    const float* w = W_pre + l * 512;
    float acc = b_pre[l];
    for (int d = 0; d < 256; d++)
        acc += pe[t * 256 + d] * w[d] + emb[t * 256 + d] * w[256 + d];
    g_Cm[t * 256 + l] = acc;
}

__global__ void precompzW_k(const float* __restrict__ z, const float* __restrict__ W_pre)
{
    int b = blockIdx.x, l = threadIdx.x;
    const float* w = W_pre + l * 512;
    float acc = 0.f;
    for (int d = 0; d < 256; d++)
        acc += z[b * 256 + d] * w[d];
    g_zWT[l * BATCH + b] = acc;
}

__global__ void zero_k(float* p, int n)
{
    int i = blockIdx.x * blockDim.x + threadIdx.x;
    if (i < n) p[i] = 0.f;
}

// ---------------- persistent pipelined 2-layer GRU (direct-L2 h reads) -----
// 128 CTAs x 384 thr, 1 CTA/SM. CTA owns j rows bx*4..bx*4+3 for all 3 mats.
// Thread: grp = tid/128 (mat: 0=Whh0/h1, 1=Wih1/h1, 2=Whh1/h2);
//         r = tid%128, p = r>>6 (j-pair), q = r&63, b0 = 2q (2 batch elems).
// h is read DIRECTLY from L2 via ld.global.cg (each h address is written once
// at step t and read once at step t+1 — no reuse, no L1-staleness risk, and
// no TMA/ring/mbarrier apparatus). Weights live in smem (one LDS.128
// broadcast per gate per warp per 2-k). Every accumulator is one full
// ascending-k fma2 chain (bitwise = R14); m1 group hands gi1 partials to m2
// group via a small smem buffer (pure value move).
// Smem: 72KB packed weight pairs + 6KB exchange = 79872 B.
__global__ void __launch_bounds__(384, 1)
rnn_pipe(const float* __restrict__ Whh0, const float* __restrict__ Whh1,
         const float* __restrict__ Wih1,
         const float* __restrict__ bih0, const float* __restrict__ bhh0,
         const float* __restrict__ bih1, const float* __restrict__ bhh1,
         const int* __restrict__ n_nodes)
{
    extern __shared__ float sm[];
    u64* sw2 = (u64*)sm;                 // 9216 u64 = 72KB
    u64* ex  = (u64*)(sm + 18432);       // 768 u64 = 6KB

    const int tid = threadIdx.x;
    const int bx  = blockIdx.x;
    const int grp = tid / 128;           // mat group 0/1/2
    const int r   = tid % 128;
    const int p   = r >> 6;              // j-pair 0/1
    const int q   = r & 63;
    const int b0  = q * 2;
    const int jA  = bx*4 + 2*p;

    // stage packed weight pairs: row = (m*3+g)*2 + pr, lanes {j even, j odd}
    for (int i = tid; i < 9216; i += 384) {
        int row = i >> 9, k = i & 511;
        int mg = row >> 1, pr = row & 1;
        int m = mg / 3, g = mg % 3;
        const float* W = (m == 0) ? Whh0 : (m == 1) ? Wih1 : Whh1;
        size_t r0 = (size_t)(g*512 + bx*4 + 2*pr) * 512 + k;
        sw2[i] = packab(W[r0], W[r0 + 512]);
    }
    __syncthreads();

    // this thread's 3 weight-row pointers (its mat, 3 gates, its j-pair)
    const u64* wg0 = sw2 + (size_t)((grp*3 + 0)*2 + p)*512;
    const u64* wg1 = sw2 + (size_t)((grp*3 + 1)*2 + p)*512;
    const u64* wg2 = sw2 + (size_t)((grp*3 + 2)*2 + p)*512;

    // per-thread constants (by group)
    float bi0[2][3], bh0[2][3], bi1[2][3], bh1[2][3], at_[2][3][2];
    int2 nn2 = make_int2(0, 0);
    if (grp == 0) {
        nn2 = *(const int2*)(n_nodes + b0);
#pragma unroll
        for (int l = 0; l < 2; l++) {
            int j = jA + l;
#pragma unroll
            for (int gg = 0; gg < 3; gg++) {
                bi0[l][gg] = bih0[gg*512 + j]; bh0[l][gg] = bhh0[gg*512 + j];
                float2 a2 = *(const float2*)(g_AT + (size_t)(gg*512 + j)*128 + b0);
                at_[l][gg][0] = a2.x; at_[l][gg][1] = a2.y;
            }
        }
    } else if (grp == 2) {
#pragma unroll
        for (int l = 0; l < 2; l++) {
            int j = jA + l;
#pragma unroll
            for (int gg = 0; gg < 3; gg++) {
                bi1[l][gg] = bih1[gg*512 + j]; bh1[l][gg] = bhh1[gg*512 + j];
            }
        }
    }
    float h1p[2][2] = {{0.f,0.f},{0.f,0.f}};   // [l][i] (grp0)
    float h2p[2][2] = {{0.f,0.f},{0.f,0.f}};   // [l][i] (grp2)

    for (int s = 0; s <= 64; s++) {
        const float* b1 = (s >= 1) ? g_h1T + (size_t)(s-1)*HB : g_zH;
        const float* b2 = (s >= 2) ? g_h2T + (size_t)(s-2)*HB : g_zH;
        const float* hs = ((grp == 2) ? b2 : b1) + b0;
        u64 acc[3][2] = {{0,0},{0,0},{0,0}};   // [gate][b-index]

        // prefetch D for gate0 (grp0 only; consumed ~20K cycles later)
        float dpre[2][3];
        if (grp == 0 && s < 64) {
#pragma unroll
            for (int l = 0; l < 2; l++) {
                dpre[l][0] = __ldg(g_D + (size_t)s*G3 + jA + l);
                dpre[l][1] = __ldg(g_D + (size_t)s*G3 + 512 + jA + l);
                dpre[l][2] = __ldg(g_D + (size_t)s*G3 + 1024 + jA + l);
            }
        }

        // ---- main GEMM: 512 k, h streamed from L2 (.cg), weights from smem
#pragma unroll 8
        for (int k2 = 0; k2 < 256; k2++) {
            const int kk = k2 * 2;
            ulonglong2 wv0 = *(const ulonglong2*)(wg0 + kk);
            ulonglong2 wv1 = *(const ulonglong2*)(wg1 + kk);
            ulonglong2 wv2 = *(const ulonglong2*)(wg2 + kk);
            u64 hp0 = ldcg64(hs + (size_t)kk*128);
            u64 hp1 = ldcg64(hs + (size_t)(kk+1)*128);
            float2 h0f = unpk(hp0), h1f = unpk(hp1);
            u64 a0 = pack2(h0f.x), b0v = pack2(h0f.y);
            u64 a1 = pack2(h1f.x), b1v = pack2(h1f.y);
            fma2(acc[0][0], wv0.x, a0);  fma2(acc[0][0], wv0.y, a1);
            fma2(acc[1][0], wv1.x, a0);  fma2(acc[1][0], wv1.y, a1);
            fma2(acc[2][0], wv2.x, a0);  fma2(acc[2][0], wv2.y, a1);
            fma2(acc[0][1], wv0.x, b0v); fma2(acc[0][1], wv0.y, b1v);
            fma2(acc[1][1], wv1.x, b0v); fma2(acc[1][1], wv1.y, b1v);
            fma2(acc[2][1], wv2.x, b0v); fma2(acc[2][1], wv2.y, b1v);
        }

        // ---- m1 group hands gi1 partials to m2 group (pure value move) ----
        if (grp == 1) {
#pragma unroll
            for (int gg = 0; gg < 3; gg++) {
                ex[(r*3 + gg)*2]     = acc[gg][0];
                ex[(r*3 + gg)*2 + 1] = acc[gg][1];
            }
        }
        __syncthreads();

        if (grp == 0 && s < 64) {   // gate0, t = s
            int t = s;
            float2 vR0 = unpk(acc[0][0]), vR1 = unpk(acc[0][1]);
            float2 vZ0 = unpk(acc[1][0]), vZ1 = unpk(acc[1][1]);
            float2 vN0 = unpk(acc[2][0]), vN1 = unpk(acc[2][1]);
            float ghr[2][2] = {{vR0.x,vR1.x},{vR0.y,vR1.y}};   // [l][i]
            float ghz[2][2] = {{vZ0.x,vZ1.x},{vZ0.y,vZ1.y}};
            float ghn[2][2] = {{vN0.x,vN1.x},{vN0.y,vN1.y}};
            int nnv[2] = {nn2.x, nn2.y};
#pragma unroll
            for (int l = 0; l < 2; l++) {
                int j = jA + l;
                float hv[2];
#pragma unroll
                for (int i = 0; i < 2; i++) {
                    float gir = bi0[l][0], giz = bi0[l][1], gin = bi0[l][2];
                    if (t < nnv[i]) {
                        gir += at_[l][0][i] + dpre[l][0];
                        giz += at_[l][1][i] + dpre[l][1];
                        gin += at_[l][2][i] + dpre[l][2];
                    }
                    float R = ghr[l][i]+bh0[l][0], Z = ghz[l][i]+bh0[l][1], N = ghn[l][i]+bh0[l][2];
                    float rr = sigm(gir+R), zz = sigm(giz+Z), nl = tanhf(gin + rr*N);
                    float h = (1.f - zz)*nl + zz*h1p[l][i];
                    h1p[l][i] = h; hv[i] = h;
                }
                *(float2*)(g_h1T + (size_t)s*HB + (size_t)j*128 + b0) = make_float2(hv[0], hv[1]);
            }
        }
        if (grp == 2 && s >= 1) {   // gate1, t = s-1
            u64 giu[3][2];
#pragma unroll
            for (int gg = 0; gg < 3; gg++) {
                giu[gg][0] = ex[(r*3 + gg)*2];
                giu[gg][1] = ex[(r*3 + gg)*2 + 1];
            }
            float2 iR0 = unpk(giu[0][0]), iR1 = unpk(giu[0][1]);
            float2 iZ0 = unpk(giu[1][0]), iZ1 = unpk(giu[1][1]);
            float2 iN0 = unpk(giu[2][0]), iN1 = unpk(giu[2][1]);
            float2 hR0 = unpk(acc[0][0]), hR1 = unpk(acc[0][1]);
            float2 hZ0 = unpk(acc[1][0]), hZ1 = unpk(acc[1][1]);
            float2 hN0 = unpk(acc[2][0]), hN1 = unpk(acc[2][1]);
            float giR[2][2] = {{iR0.x,iR1.x},{iR0.y,iR1.y}};
            float giZ[2][2] = {{iZ0.x,iZ1.x},{iZ0.y,iZ1.y}};
            float giN[2][2] = {{iN0.x,iN1.x},{iN0.y,iN1.y}};
            float ghR[2][2] = {{hR0.x,hR1.x},{hR0.y,hR1.y}};
            float ghZ[2][2] = {{hZ0.x,hZ1.x},{hZ0.y,hZ1.y}};
            float ghN[2][2] = {{hN0.x,hN1.x},{hN0.y,hN1.y}};
#pragma unroll
            for (int l = 0; l < 2; l++) {
                int j = jA + l;
                float hv[2];
#pragma unroll
                for (int i = 0; i < 2; i++) {
                    float gir = giR[l][i]+bi1[l][0], giz = giZ[l][i]+bi1[l][1], gin = giN[l][i]+bi1[l][2];
                    float R = ghR[l][i]+bh1[l][0], Z = ghZ[l][i]+bh1[l][1], N = ghN[l][i]+bh1[l][2];
                    float rr = sigm(gir+R), zz = sigm(giz+Z), nl = tanhf(gin + rr*N);
                    float h = (1.f - zz)*nl + zz*h2p[l][i];
                    h2p[l][i] = h; hv[i] = h;
                }
                *(float2*)(g_h2T + (size_t)(s-1)*HB + (size_t)j*128 + b0) = make_float2(hv[0], hv[1]);
            }
        }
        gridbar();
    }
}

// ---------------- fused U/V GEMM (f32x2, PQt pre-packed) -------------------
__global__ void __launch_bounds__(256, 2)
uv_k(const float* __restrict__ adj_b1)
{
    extern __shared__ float us[];
    float* hb = us;          // 2 x 4096
    float* wb = us + 8192;   // 2 x 4096

    const int tid = threadIdx.x;
    const int t   = blockIdx.x >> 3;
    const int h0  = (blockIdx.x & 7) * 128;
    const int bg  = tid & 31, hg = tid >> 5;
    const int b0  = bg * 4;
    const float* hsrc = g_h2T + (size_t)t*HB;
    const float* wsrc = g_PQt + h0;

    u64 acc[8][4] = {};

#define UV_PF(c) { \
    float* hd = hb + ((c)&1)*4096; \
    float* wd = wb + ((c)&1)*4096; \
    _Pragma("unroll") for (int i = 0; i < 4; i++) { \
        int l = tid + 256*i; int row = l >> 5, c4 = l & 31; \
        cp16(hd + l*4, hsrc + (size_t)((c)*32 + row)*128  + c4*4); \
        cp16(wd + l*4, wsrc + (size_t)((c)*32 + row)*1024 + c4*4); \
    } cp_commit(); }

    UV_PF(0); UV_PF(1);
    for (int c = 0; c < 16; c++) {
        if (c < 15) cp_wait1(); else cp_wait0();
        __syncthreads();
        const float* hh = hb + (c&1)*4096;
        const float* ww = wb + (c&1)*4096;
#pragma unroll 4
        for (int kk = 0; kk < 32; kk++) {
            u64 w[8];
#pragma unroll
            for (int pp = 0; pp < 8; pp++)
                w[pp] = *(const u64*)(ww + kk*128 + hg*16 + pp*2);
            float4 hv4 = *(const float4*)(hh + kk*128 + b0);
            u64 hv[4];
            hv[0] = pack2(hv4.x); hv[1] = pack2(hv4.y);
            hv[2] = pack2(hv4.z); hv[3] = pack2(hv4.w);
#pragma unroll
            for (int pp = 0; pp < 8; pp++)
#pragma unroll
                for (int i = 0; i < 4; i++)
                    fma2(acc[pp][i], w[pp], hv[i]);
        }
        __syncthreads();
        if (c + 2 < 16) UV_PF(c + 2);
    }

#pragma unroll
    for (int pp = 0; pp < 8; pp++) {
        int hloc = h0 + hg*16 + pp*2;
#pragma unroll
        for (int i = 0; i < 4; i++) {
            float2 v = unpk(acc[pp][i]);
            int bb = b0 + i;
            if (hloc < 512) {
                *(float2*)(g_U + ((size_t)bb*64 + t)*512 + hloc) = v;
            } else {
                v.x += adj_b1[hloc - 512];
                v.y += adj_b1[hloc - 511];
                *(float2*)(g_V + ((size_t)bb*64 + t)*512 + (hloc - 512)) = v;
            }
        }
    }
}

// ---------------- pair kernel (unchanged numerics) -------------------------
__global__ void pair_k(const float* __restrict__ W2, const float* __restrict__ b2,
                       const float* __restrict__ gu, const int* __restrict__ n_nodes,
                       float* __restrict__ out)
{
    int b    = blockIdx.x;
    int warp = (int)(blockIdx.y * 8 + (threadIdx.x >> 5));
    int lane = threadIdx.x & 31;
    int nb   = n_nodes[b];
    float* ob = out + (long)b * (MNODES * MNODES);

    float4 w2a[4], w2b[4];
#pragma unroll
    for (int q = 0; q < 4; q++) {
        w2a[q] = *(const float4*)(W2 + 4 * lane + 128 * q);
        w2b[q] = *(const float4*)(W2 + HIDDEN + 4 * lane + 128 * q);
    }
    for (int pp = warp; pp < NPAIRS; pp += 32) {
        int jn = g_jj[pp];
        if (jn >= nb) continue;
        int in = g_ii[pp];
        const float* Ui = g_U + ((long)b * MNODES + in) * HIDDEN;
        const float* Vj = g_V + ((long)b * MNODES + jn) * HIDDEN;
        float a0 = 0.f, a1 = 0.f;
#pragma unroll
        for (int q = 0; q < 4; q++) {
            float4 u = *(const float4*)(Ui + 4 * lane + 128 * q);
            float4 v = *(const float4*)(Vj + 4 * lane + 128 * q);
            float m;
            m = fmaxf(u.x + v.x, 0.f); a0 = fmaf(m, w2a[q].x, a0); a1 = fmaf(m, w2b[q].x, a1);
            m = fmaxf(u.y + v.y, 0.f); a0 = fmaf(m, w2a[q].y, a0); a1 = fmaf(m, w2b[q].y, a1);
            m = fmaxf(u.z + v.z, 0.f); a0 = fmaf(m, w2a[q].z, a0); a1 = fmaf(m, w2b[q].z, a1);
            m = fmaxf(u.w + v.w, 0.f); a0 = fmaf(m, w2a[q].w, a0); a1 = fmaf(m, w2b[q].w, a1);
        }
#pragma unroll
        for (int sft = 16; sft > 0; sft >>= 1) {
            a0 += __shfl_xor_sync(0xffffffffu, a0, sft);
            a1 += __shfl_xor_sync(0xffffffffu, a1, sft);
        }
        if (lane == 0) {
            float l0 = a0 + b2[0];
            float l1 = a1 + b2[1];
            const float* g = gu + ((long)b * NPAIRS + pp) * 2;
            float g0 = -logf(-logf(g[0] + 1e-10f) + 1e-10f);
            float g1 = -logf(-logf(g[1] + 1e-10f) + 1e-10f);
            if (l0 + g0 >= l1 + g1) {
                ob[in * MNODES + jn] = 1.f;
                ob[jn * MNODES + in] = 1.f;
            }
        }
    }
}

// ---------------- host launch sequence -------------------------------------
extern "C" void kernel_launch(void* const* d_in, const int* in_sizes, int n_in,
                              void* d_out, int out_size)
{
    const float* z       = (const float*)d_in[0];
    const int*   n_nodes = (const int*)  d_in[1];
    const float* gu      = (const float*)d_in[3];
    const float* emb     = (const float*)d_in[4];
    const float* pe      = (const float*)d_in[5];
    const float* W_pre   = (const float*)d_in[6];
    const float* b_pre   = (const float*)d_in[7];
    const float* Wih0    = (const float*)d_in[8];
    const float* Whh0    = (const float*)d_in[9];
    const float* bih0    = (const float*)d_in[10];
    const float* bhh0    = (const float*)d_in[11];
    const float* Wih1    = (const float*)d_in[12];
    const float* Whh1    = (const float*)d_in[13];
    const float* bih1    = (const float*)d_in[14];
    const float* bhh1    = (const float*)d_in[15];
    const float* node_W  = (const float*)d_in[16];
    const float* adj_W1  = (const float*)d_in[17];
    const float* adj_b1  = (const float*)d_in[18];
    const float* adj_W2  = (const float*)d_in[19];
    const float* adj_b2  = (const float*)d_in[20];
    float* out = (float*)d_out;

    float *PQt;
    cudaGetSymbolAddress((void**)&PQt, g_PQt);

    static int attr_set = 0;
    if (!attr_set) {
        cudaFuncSetAttribute(rnn_pipe, cudaFuncAttributeMaxDynamicSharedMemorySize, 79872);
        cudaFuncSetAttribute(uv_k,     cudaFuncAttributeMaxDynamicSharedMemorySize, 65536);
        attr_set = 1;
    }

    // 1-3: prolog (positions rnn_pipe as 4th launch for ncu -s capture)
    precompC_k<<<MNODES, 256>>>(pe, emb, W_pre, b_pre);
    precompzW_k<<<BATCH, 256>>>(z, W_pre);
    ATD_k<<<121, 256>>>(Wih0);

    // 4: fused pipelined recurrence (persistent, direct-L2 h reads)
    rnn_pipe<<<128, 384, 79872>>>(Whh0, Whh1, Wih1, bih0, bhh0, bih1, bhh1, n_nodes);

    // 5-6: PQt[k][h'] = P^T | Q^T
    sgemm_k<64, 64, 16, 4, 4, false, true><<<dim3(8, 8), 256>>>(
        node_W, adj_W1, PQt, nullptr, HIDDEN, HIDDEN, 2 * HIDDEN, 1024);
    sgemm_k<64, 64, 16, 4, 4, false, true><<<dim3(8, 8), 256>>>(
        node_W, adj_W1 + HIDDEN, PQt + 512, nullptr, HIDDEN, HIDDEN, 2 * HIDDEN, 1024);

    // 7: fused U/V
    uv_k<<<512, 256, 65536>>>(adj_b1);

    // 8-9: output
    zero_k<<<(BATCH * MNODES * MNODES + 255) / 256, 256>>>(out, BATCH * MNODES * MNODES);
    pair_k<<<dim3(BATCH, 4), 256>>>(adj_W2, adj_b2, gu, n_nodes, out);
}

// round 17
// speedup vs baseline: 1.5323x; 1.0850x over previous
#include <cuda_runtime.h>
#include <stdint.h>
#include <math.h>

#define BATCH  128
#define LATENT 256
#define HIDDEN 512
#define MNODES 64
#define NPAIRS 2016
#define G3     1536
#define HB     65536

typedef unsigned long long u64;

// ---------------- device scratch (zero-initialized at load) ----------------
__device__ __align__(16) float g_Cm [MNODES*LATENT];
__device__ __align__(16) float g_zWT[LATENT*BATCH];
__device__ __align__(16) float g_AT [G3*BATCH];        // [g][b]
__device__ __align__(16) float g_D  [MNODES*G3];       // [t][g]
__device__ __align__(16) float g_PQt[HIDDEN*1024];     // [k][h'] P|Q transposed
__device__ __align__(16) float g_h1T[MNODES*HB];       // [t][k][b]
__device__ __align__(16) float g_h2T[MNODES*HB];       // [t][k][b]
__device__ __align__(16) float g_zH [HB];              // stays all-zero
__device__ __align__(16) float g_U  [BATCH*MNODES*HIDDEN];
__device__ __align__(16) float g_V  [BATCH*MNODES*HIDDEN];
__device__ int g_ii[NPAIRS];
__device__ int g_jj[NPAIRS];
__device__ unsigned g_bar_cnt;   // monotonic ticket counter (never reset)

// ---------------- f32x2 helpers (lanes = independent IEEE fma chains) ------
__device__ __forceinline__ u64 pack2(float x){u64 r;asm("mov.b64 %0,{%1,%1};":"=l"(r):"f"(x));return r;}
__device__ __forceinline__ void fma2(u64&a,u64 b,u64 c){asm("fma.rn.f32x2 %0, %1, %2, %0;":"+l"(a):"l"(b),"l"(c));}
__device__ __forceinline__ float2 unpk(u64 v){float2 f;asm("mov.b64 {%0,%1},%2;":"=f"(f.x),"=f"(f.y):"l"(v));return f;}
__device__ __forceinline__ u64 packab(float a,float b){u64 r;asm("mov.b64 %0,{%1,%2};":"=l"(r):"f"(a),"f"(b));return r;}
__device__ __forceinline__ float sigm(float x){return 1.f/(1.f+expf(-x));}

// ---------------- ticket grid barrier (replay-safe, no reset needed) -------
__device__ __forceinline__ void gridbar()
{
    __threadfence();
    __syncthreads();
    if (threadIdx.x == 0) {
        unsigned t = atomicAdd(&g_bar_cnt, 1u);
        unsigned target = (t & ~127u) + 128u;
        while (*(volatile unsigned*)&g_bar_cnt < target) __nanosleep(32);
        __threadfence();
    }
    __syncthreads();
}

// ---------------- cp.async.cg (16B, L2-coherent) — used by uv_k ------------
__device__ __forceinline__ void cp16(void* smem, const void* gmem){
    unsigned s = (unsigned)__cvta_generic_to_shared(smem);
    asm volatile("cp.async.cg.shared.global [%0], [%1], 16;" :: "r"(s), "l"(gmem) : "memory");
}
__device__ __forceinline__ void cp_commit(){ asm volatile("cp.async.commit_group;" ::: "memory"); }
__device__ __forceinline__ void cp_wait0(){ asm volatile("cp.async.wait_group 0;" ::: "memory"); }
__device__ __forceinline__ void cp_wait1(){ asm volatile("cp.async.wait_group 1;" ::: "memory"); }

// ---------------- generic tiled fp32 GEMM body (ascending-k chain) ---------
template<int BM, int BN, int BK, int TM, int TN, bool A_ROW, bool B_NK>
__device__ __forceinline__ void sgemm_dev(const float* __restrict__ A, const float* __restrict__ B,
                                          float* __restrict__ C, const float* __restrict__ bias,
                                          int K, int lda, int ldb, int ldc, int m0, int n0,
                                          float* sms)
{
    float* As = sms;
    float* Bs = sms + BM * BK;
    constexpr int NTH = (BM / TM) * (BN / TN);
    const int tid  = threadIdx.x;
    const int tcol = tid % (BN / TN);
    const int trow = tid / (BN / TN);
    float acc[TM][TN];
#pragma unroll
    for (int i = 0; i < TM; i++)
#pragma unroll
        for (int jx = 0; jx < TN; jx++) acc[i][jx] = 0.f;
    for (int k0 = 0; k0 < K; k0 += BK) {
#pragma unroll
        for (int idx = tid; idx < BM * BK; idx += NTH) {
            int m = idx / BK, kk = idx % BK;
            As[kk*BM + m] = A_ROW ? A[(long)(m0 + m) * lda + (k0 + kk)]
                                  : A[(long)(k0 + kk) * lda + (m0 + m)];
        }
#pragma unroll
        for (int idx = tid; idx < BK * BN; idx += NTH) {
            int kk = idx / BN, n = idx % BN;
            Bs[kk*BN + n] = B_NK ? B[(long)(n0 + n) * ldb + (k0 + kk)]
                                 : B[(long)(k0 + kk) * ldb + (n0 + n)];
        }
        __syncthreads();
#pragma unroll
        for (int kk = 0; kk < BK; kk++) {
            float a[TM], bb[TN];
#pragma unroll
            for (int i = 0; i < TM; i++) a[i] = As[kk*BM + trow * TM + i];
#pragma unroll
            for (int jx = 0; jx < TN; jx++) bb[jx] = Bs[kk*BN + tcol * TN + jx];
#pragma unroll
            for (int i = 0; i < TM; i++)
#pragma unroll
                for (int jx = 0; jx < TN; jx++)
                    acc[i][jx] = fmaf(a[i], bb[jx], acc[i][jx]);
        }
        __syncthreads();
    }
#pragma unroll
    for (int i = 0; i < TM; i++) {
        int m = m0 + trow * TM + i;
#pragma unroll
        for (int jx = 0; jx < TN; jx++) {
            int n = n0 + tcol * TN + jx;
            float v = acc[i][jx];
            if (bias) v += bias[n];
            C[(long)m * ldc + n] = v;
        }
    }
}

// ---------------- prolog fused kernel: AT + D + pairidx --------------------
__global__ void ATD_k(const float* __restrict__ Wih0)
{
    __shared__ float sms[2048];
    int bx = blockIdx.x;
    if (bx < 96) {
        sgemm_dev<64,32,16,4,2,true,false>(Wih0, g_zWT, g_AT, nullptr,
            LATENT, LATENT, BATCH, BATCH, (bx>>2)*64, (bx&3)*32, sms);
    } else if (bx < 120) {
        sgemm_dev<64,64,16,4,4,true,true>(g_Cm, Wih0, g_D, nullptr,
            LATENT, LATENT, LATENT, G3, 0, (bx-96)*64, sms);
    } else {
        for (int p = threadIdx.x; p < NPAIRS; p += 256) {
            int i = 0, rem = p;
            while (rem >= 63 - i) { rem -= 63 - i; i++; }
            g_ii[p] = i;
            g_jj[p] = i + 1 + rem;
        }
    }
}

// ---------------- PQt kernel (z-batched over halves, runs on side stream) --
__global__ void pqt_k(const float* __restrict__ node_W, const float* __restrict__ adj_W1)
{
    __shared__ float sms[2048];
    int z = blockIdx.z;
    sgemm_dev<64,64,16,4,4,false,true>(node_W, adj_W1 + z*HIDDEN, g_PQt + z*HIDDEN, nullptr,
        HIDDEN, HIDDEN, 2*HIDDEN, 1024, blockIdx.y*64, blockIdx.x*64, sms);
}

// ---------------- small precompute kernels ---------------------------------
__global__ void precompC_k(const float* __restrict__ pe, const float* __restrict__ emb,
                           const float* __restrict__ W_pre, const float* __restrict__ b_pre)
{
    int t = blockIdx.x, l = threadIdx.x;
    const float* w = W_pre + l * 512;
    float acc = b_pre[l];
    for (int d = 0; d < 256; d++)
        acc += pe[t * 256 + d] * w[d] + emb[t * 256 + d] * w[256 + d];
    g_Cm[t * 256 + l] = acc;
}

__global__ void precompzW_k(const float* __restrict__ z, const float* __restrict__ W_pre)
{
    int b = blockIdx.x, l = threadIdx.x;
    const float* w = W_pre + l * 512;
    float acc = 0.f;
    for (int d = 0; d < 256; d++)
        acc += z[b * 256 + d] * w[d];
    g_zWT[l * BATCH + b] = acc;
}

__global__ void zero_k(float* p, int n)
{
    int i = blockIdx.x * blockDim.x + threadIdx.x;
    if (i < n) p[i] = 0.f;
}

// ---------------- persistent pipelined 2-layer GRU (direct-L2 h reads) -----
// 128 CTAs x 384 thr, 1 CTA/SM. CTA owns j rows bx*4..bx*4+3 for all 3 mats.
// Thread: grp = tid/128 (mat: 0=Whh0/h1, 1=Wih1/h1, 2=Whh1/h2);
//         r = tid%128, p = r>>6 (j-pair), q = r&63, b0 = 2q (2 batch elems).
// h is read from L2 via schedulable __ldcg through an explicit distance-4
// register ring (8 LDG.64 in flight per thread) so load latency overlaps the
// fma2 stream. Weights in smem. Every accumulator is one full ascending-k
// fma2 chain (bitwise = R15); m1 group hands gi1 partials to m2 group via a
// small smem buffer (pure value move). Smem 78KB.
__global__ void __launch_bounds__(384, 1)
rnn_pipe(const float* __restrict__ Whh0, const float* __restrict__ Whh1,
         const float* __restrict__ Wih1,
         const float* __restrict__ bih0, const float* __restrict__ bhh0,
         const float* __restrict__ bih1, const float* __restrict__ bhh1,
         const int* __restrict__ n_nodes)
{
    extern __shared__ float sm[];
    u64* sw2 = (u64*)sm;                 // 9216 u64 = 72KB
    u64* ex  = (u64*)(sm + 18432);       // 768 u64 = 6KB

    const int tid = threadIdx.x;
    const int bx  = blockIdx.x;
    const int grp = tid / 128;           // mat group 0/1/2
    const int r   = tid % 128;
    const int p   = r >> 6;              // j-pair 0/1
    const int q   = r & 63;
    const int b0  = q * 2;
    const int jA  = bx*4 + 2*p;

    // stage packed weight pairs: row = (m*3+g)*2 + pr, lanes {j even, j odd}
    for (int i = tid; i < 9216; i += 384) {
        int row = i >> 9, k = i & 511;
        int mg = row >> 1, pr = row & 1;
        int m = mg / 3, g = mg % 3;
        const float* W = (m == 0) ? Whh0 : (m == 1) ? Wih1 : Whh1;
        size_t r0 = (size_t)(g*512 + bx*4 + 2*pr) * 512 + k;
        sw2[i] = packab(W[r0], W[r0 + 512]);
    }
    __syncthreads();

    const u64* wg0 = sw2 + (size_t)((grp*3 + 0)*2 + p)*512;
    const u64* wg1 = sw2 + (size_t)((grp*3 + 1)*2 + p)*512;
    const u64* wg2 = sw2 + (size_t)((grp*3 + 2)*2 + p)*512;

    // per-thread constants (by group)
    float bi0[2][3], bh0[2][3], bi1[2][3], bh1[2][3], at_[2][3][2];
    int2 nn2 = make_int2(0, 0);
    if (grp == 0) {
        nn2 = *(const int2*)(n_nodes + b0);
#pragma unroll
        for (int l = 0; l < 2; l++) {
            int j = jA + l;
#pragma unroll
            for (int gg = 0; gg < 3; gg++) {
                bi0[l][gg] = bih0[gg*512 + j]; bh0[l][gg] = bhh0[gg*512 + j];
                float2 a2 = *(const float2*)(g_AT + (size_t)(gg*512 + j)*128 + b0);
                at_[l][gg][0] = a2.x; at_[l][gg][1] = a2.y;
            }
        }
    } else if (grp == 2) {
#pragma unroll
        for (int l = 0; l < 2; l++) {
            int j = jA + l;
#pragma unroll
            for (int gg = 0; gg < 3; gg++) {
                bi1[l][gg] = bih1[gg*512 + j]; bh1[l][gg] = bhh1[gg*512 + j];
            }
        }
    }
    float h1p[2][2] = {{0.f,0.f},{0.f,0.f}};
    float h2p[2][2] = {{0.f,0.f},{0.f,0.f}};

    for (int s = 0; s <= 64; s++) {
        const float* b1 = (s >= 1) ? g_h1T + (size_t)(s-1)*HB : g_zH;
        const float* b2 = (s >= 2) ? g_h2T + (size_t)(s-2)*HB : g_zH;
        const float* hs = ((grp == 2) ? b2 : b1) + b0;
        u64 acc[3][2] = {{0,0},{0,0},{0,0}};

        float dpre[2][3];
        if (grp == 0 && s < 64) {
#pragma unroll
            for (int l = 0; l < 2; l++) {
                dpre[l][0] = __ldg(g_D + (size_t)s*G3 + jA + l);
                dpre[l][1] = __ldg(g_D + (size_t)s*G3 + 512 + jA + l);
                dpre[l][2] = __ldg(g_D + (size_t)s*G3 + 1024 + jA + l);
            }
        }

        // ---- main GEMM: 512 k; h via __ldcg with distance-4 register ring
        float2 hq[4][2];
#pragma unroll
        for (int d = 0; d < 4; d++) {
            hq[d][0] = __ldcg((const float2*)(hs + (size_t)(2*d)*128));
            hq[d][1] = __ldcg((const float2*)(hs + (size_t)(2*d+1)*128));
        }
#pragma unroll 8
        for (int k2 = 0; k2 < 256; k2++) {
            const int kk = k2 * 2;
            float2 c0 = hq[k2 & 3][0];
            float2 c1 = hq[k2 & 3][1];
            if (k2 < 252) {
                hq[k2 & 3][0] = __ldcg((const float2*)(hs + (size_t)(kk+8)*128));
                hq[k2 & 3][1] = __ldcg((const float2*)(hs + (size_t)(kk+9)*128));
            }
            ulonglong2 wv0 = *(const ulonglong2*)(wg0 + kk);
            ulonglong2 wv1 = *(const ulonglong2*)(wg1 + kk);
            ulonglong2 wv2 = *(const ulonglong2*)(wg2 + kk);
            u64 a0 = pack2(c0.x), b0v = pack2(c0.y);
            u64 a1 = pack2(c1.x), b1v = pack2(c1.y);
            fma2(acc[0][0], wv0.x, a0);  fma2(acc[0][0], wv0.y, a1);
            fma2(acc[1][0], wv1.x, a0);  fma2(acc[1][0], wv1.y, a1);
            fma2(acc[2][0], wv2.x, a0);  fma2(acc[2][0], wv2.y, a1);
            fma2(acc[0][1], wv0.x, b0v); fma2(acc[0][1], wv0.y, b1v);
            fma2(acc[1][1], wv1.x, b0v); fma2(acc[1][1], wv1.y, b1v);
            fma2(acc[2][1], wv2.x, b0v); fma2(acc[2][1], wv2.y, b1v);
        }

        // ---- m1 group hands gi1 partials to m2 group (pure value move) ----
        if (grp == 1) {
#pragma unroll
            for (int gg = 0; gg < 3; gg++) {
                ex[(r*3 + gg)*2]     = acc[gg][0];
                ex[(r*3 + gg)*2 + 1] = acc[gg][1];
            }
        }
        __syncthreads();

        if (grp == 0 && s < 64) {   // gate0, t = s
            int t = s;
            float2 vR0 = unpk(acc[0][0]), vR1 = unpk(acc[0][1]);
            float2 vZ0 = unpk(acc[1][0]), vZ1 = unpk(acc[1][1]);
            float2 vN0 = unpk(acc[2][0]), vN1 = unpk(acc[2][1]);
            float ghr[2][2] = {{vR0.x,vR1.x},{vR0.y,vR1.y}};
            float ghz[2][2] = {{vZ0.x,vZ1.x},{vZ0.y,vZ1.y}};
            float ghn[2][2] = {{vN0.x,vN1.x},{vN0.y,vN1.y}};
            int nnv[2] = {nn2.x, nn2.y};
#pragma unroll
            for (int l = 0; l < 2; l++) {
                int j = jA + l;
                float hv[2];
#pragma unroll
                for (int i = 0; i < 2; i++) {
                    float gir = bi0[l][0], giz = bi0[l][1], gin = bi0[l][2];
                    if (t < nnv[i]) {
                        gir += at_[l][0][i] + dpre[l][0];
                        giz += at_[l][1][i] + dpre[l][1];
                        gin += at_[l][2][i] + dpre[l][2];
                    }
                    float R = ghr[l][i]+bh0[l][0], Z = ghz[l][i]+bh0[l][1], N = ghn[l][i]+bh0[l][2];
                    float rr = sigm(gir+R), zz = sigm(giz+Z), nl = tanhf(gin + rr*N);
                    float h = (1.f - zz)*nl + zz*h1p[l][i];
                    h1p[l][i] = h; hv[i] = h;
                }
                *(float2*)(g_h1T + (size_t)s*HB + (size_t)j*128 + b0) = make_float2(hv[0], hv[1]);
            }
        }
        if (grp == 2 && s >= 1) {   // gate1, t = s-1
            u64 giu[3][2];
#pragma unroll
            for (int gg = 0; gg < 3; gg++) {
                giu[gg][0] = ex[(r*3 + gg)*2];
                giu[gg][1] = ex[(r*3 + gg)*2 + 1];
            }
            float2 iR0 = unpk(giu[0][0]), iR1 = unpk(giu[0][1]);
            float2 iZ0 = unpk(giu[1][0]), iZ1 = unpk(giu[1][1]);
            float2 iN0 = unpk(giu[2][0]), iN1 = unpk(giu[2][1]);
            float2 hR0 = unpk(acc[0][0]), hR1 = unpk(acc[0][1]);
            float2 hZ0 = unpk(acc[1][0]), hZ1 = unpk(acc[1][1]);
            float2 hN0 = unpk(acc[2][0]), hN1 = unpk(acc[2][1]);
            float giR[2][2] = {{iR0.x,iR1.x},{iR0.y,iR1.y}};
            float giZ[2][2] = {{iZ0.x,iZ1.x},{iZ0.y,iZ1.y}};
            float giN[2][2] = {{iN0.x,iN1.x},{iN0.y,iN1.y}};
            float ghR[2][2] = {{hR0.x,hR1.x},{hR0.y,hR1.y}};
            float ghZ[2][2] = {{hZ0.x,hZ1.x},{hZ0.y,hZ1.y}};
            float ghN[2][2] = {{hN0.x,hN1.x},{hN0.y,hN1.y}};
#pragma unroll
            for (int l = 0; l < 2; l++) {
                int j = jA + l;
                float hv[2];
#pragma unroll
                for (int i = 0; i < 2; i++) {
                    float gir = giR[l][i]+bi1[l][0], giz = giZ[l][i]+bi1[l][1], gin = giN[l][i]+bi1[l][2];
                    float R = ghR[l][i]+bh1[l][0], Z = ghZ[l][i]+bh1[l][1], N = ghN[l][i]+bh1[l][2];
                    float rr = sigm(gir+R), zz = sigm(giz+Z), nl = tanhf(gin + rr*N);
                    float h = (1.f - zz)*nl + zz*h2p[l][i];
                    h2p[l][i] = h; hv[i] = h;
                }
                *(float2*)(g_h2T + (size_t)(s-1)*HB + (size_t)j*128 + b0) = make_float2(hv[0], hv[1]);
            }
        }
        gridbar();
    }
}

// ---------------- fused U/V GEMM (f32x2, PQt pre-packed) -------------------
__global__ void __launch_bounds__(256, 2)
uv_k(const float* __restrict__ adj_b1)
{
    extern __shared__ float us[];
    float* hb = us;          // 2 x 4096
    float* wb = us + 8192;   // 2 x 4096

    const int tid = threadIdx.x;
    const int t   = blockIdx.x >> 3;
    const int h0  = (blockIdx.x & 7) * 128;
    const int bg  = tid & 31, hg = tid >> 5;
    const int b0  = bg * 4;
    const float* hsrc = g_h2T + (size_t)t*HB;
    const float* wsrc = g_PQt + h0;

    u64 acc[8][4] = {};

#define UV_PF(c) { \
    float* hd = hb + ((c)&1)*4096; \
    float* wd = wb + ((c)&1)*4096; \
    _Pragma("unroll") for (int i = 0; i < 4; i++) { \
        int l = tid + 256*i; int row = l >> 5, c4 = l & 31; \
        cp16(hd + l*4, hsrc + (size_t)((c)*32 + row)*128  + c4*4); \
        cp16(wd + l*4, wsrc + (size_t)((c)*32 + row)*1024 + c4*4); \
    } cp_commit(); }

    UV_PF(0); UV_PF(1);
    for (int c = 0; c < 16; c++) {
        if (c < 15) cp_wait1(); else cp_wait0();
        __syncthreads();
        const float* hh = hb + (c&1)*4096;
        const float* ww = wb + (c&1)*4096;
#pragma unroll 4
        for (int kk = 0; kk < 32; kk++) {
            u64 w[8];
#pragma unroll
            for (int pp = 0; pp < 8; pp++)
                w[pp] = *(const u64*)(ww + kk*128 + hg*16 + pp*2);
            float4 hv4 = *(const float4*)(hh + kk*128 + b0);
            u64 hv[4];
            hv[0] = pack2(hv4.x); hv[1] = pack2(hv4.y);
            hv[2] = pack2(hv4.z); hv[3] = pack2(hv4.w);
#pragma unroll
            for (int pp = 0; pp < 8; pp++)
#pragma unroll
                for (int i = 0; i < 4; i++)
                    fma2(acc[pp][i], w[pp], hv[i]);
        }
        __syncthreads();
        if (c + 2 < 16) UV_PF(c + 2);
    }

#pragma unroll
    for (int pp = 0; pp < 8; pp++) {
        int hloc = h0 + hg*16 + pp*2;
#pragma unroll
        for (int i = 0; i < 4; i++) {
            float2 v = unpk(acc[pp][i]);
            int bb = b0 + i;
            if (hloc < 512) {
                *(float2*)(g_U + ((size_t)bb*64 + t)*512 + hloc) = v;
            } else {
                v.x += adj_b1[hloc - 512];
                v.y += adj_b1[hloc - 511];
                *(float2*)(g_V + ((size_t)bb*64 + t)*512 + (hloc - 512)) = v;
            }
        }
    }
}

// ---------------- pair kernel (unchanged numerics) -------------------------
__global__ void pair_k(const float* __restrict__ W2, const float* __restrict__ b2,
                       const float* __restrict__ gu, const int* __restrict__ n_nodes,
                       float* __restrict__ out)
{
    int b    = blockIdx.x;
    int warp = (int)(blockIdx.y * 8 + (threadIdx.x >> 5));
    int lane = threadIdx.x & 31;
    int nb   = n_nodes[b];
    float* ob = out + (long)b * (MNODES * MNODES);

    float4 w2a[4], w2b[4];
#pragma unroll
    for (int q = 0; q < 4; q++) {
        w2a[q] = *(const float4*)(W2 + 4 * lane + 128 * q);
        w2b[q] = *(const float4*)(W2 + HIDDEN + 4 * lane + 128 * q);
    }
    for (int pp = warp; pp < NPAIRS; pp += 32) {
        int jn = g_jj[pp];
        if (jn >= nb) continue;
        int in = g_ii[pp];
        const float* Ui = g_U + ((long)b * MNODES + in) * HIDDEN;
        const float* Vj = g_V + ((long)b * MNODES + jn) * HIDDEN;
        float a0 = 0.f, a1 = 0.f;
#pragma unroll
        for (int q = 0; q < 4; q++) {
            float4 u = *(const float4*)(Ui + 4 * lane + 128 * q);
            float4 v = *(const float4*)(Vj + 4 * lane + 128 * q);
            float m;
            m = fmaxf(u.x + v.x, 0.f); a0 = fmaf(m, w2a[q].x, a0); a1 = fmaf(m, w2b[q].x, a1);
            m = fmaxf(u.y + v.y, 0.f); a0 = fmaf(m, w2a[q].y, a0); a1 = fmaf(m, w2b[q].y, a1);
            m = fmaxf(u.z + v.z, 0.f); a0 = fmaf(m, w2a[q].z, a0); a1 = fmaf(m, w2b[q].z, a1);
            m = fmaxf(u.w + v.w, 0.f); a0 = fmaf(m, w2a[q].w, a0); a1 = fmaf(m, w2b[q].w, a1);
        }
#pragma unroll
        for (int sft = 16; sft > 0; sft >>= 1) {
            a0 += __shfl_xor_sync(0xffffffffu, a0, sft);
            a1 += __shfl_xor_sync(0xffffffffu, a1, sft);
        }
        if (lane == 0) {
            float l0 = a0 + b2[0];
            float l1 = a1 + b2[1];
            const float* g = gu + ((long)b * NPAIRS + pp) * 2;
            float g0 = -logf(-logf(g[0] + 1e-10f) + 1e-10f);
            float g1 = -logf(-logf(g[1] + 1e-10f) + 1e-10f);
            if (l0 + g0 >= l1 + g1) {
                ob[in * MNODES + jn] = 1.f;
                ob[jn * MNODES + in] = 1.f;
            }
        }
    }
}

// ---------------- host launch sequence -------------------------------------
extern "C" void kernel_launch(void* const* d_in, const int* in_sizes, int n_in,
                              void* d_out, int out_size)
{
    const float* z       = (const float*)d_in[0];
    const int*   n_nodes = (const int*)  d_in[1];
    const float* gu      = (const float*)d_in[3];
    const float* emb     = (const float*)d_in[4];
    const float* pe      = (const float*)d_in[5];
    const float* W_pre   = (const float*)d_in[6];
    const float* b_pre   = (const float*)d_in[7];
    const float* Wih0    = (const float*)d_in[8];
    const float* Whh0    = (const float*)d_in[9];
    const float* bih0    = (const float*)d_in[10];
    const float* bhh0    = (const float*)d_in[11];
    const float* Wih1    = (const float*)d_in[12];
    const float* Whh1    = (const float*)d_in[13];
    const float* bih1    = (const float*)d_in[14];
    const float* bhh1    = (const float*)d_in[15];
    const float* node_W  = (const float*)d_in[16];
    const float* adj_W1  = (const float*)d_in[17];
    const float* adj_b1  = (const float*)d_in[18];
    const float* adj_W2  = (const float*)d_in[19];
    const float* adj_b2  = (const float*)d_in[20];
    float* out = (float*)d_out;

    static cudaStream_t s1;
    static cudaEvent_t e0, e1;
    static int init_done = 0;
    if (!init_done) {
        cudaFuncSetAttribute(rnn_pipe, cudaFuncAttributeMaxDynamicSharedMemorySize, 79872);
        cudaFuncSetAttribute(uv_k,     cudaFuncAttributeMaxDynamicSharedMemorySize, 65536);
        cudaStreamCreateWithFlags(&s1, cudaStreamNonBlocking);
        cudaEventCreateWithFlags(&e0, cudaEventDisableTiming);
        cudaEventCreateWithFlags(&e1, cudaEventDisableTiming);
        init_done = 1;
    }

    // main stream: prolog (rnn_pipe stays launch #6 incl. 2 harness memsets)
    precompC_k<<<MNODES, 256>>>(pe, emb, W_pre, b_pre);
    precompzW_k<<<BATCH, 256>>>(z, W_pre);
    ATD_k<<<121, 256>>>(Wih0);
    cudaEventRecord(e0, 0);

    // persistent recurrence (main stream)
    rnn_pipe<<<128, 384, 79872>>>(Whh0, Whh1, Wih1, bih0, bhh0, bih1, bhh1, n_nodes);

    // side stream: PQt + output zero, concurrent with the recurrence
    cudaStreamWaitEvent(s1, e0, 0);
    pqt_k<<<dim3(8, 8, 2), 256, 0, s1>>>(node_W, adj_W1);
    zero_k<<<(BATCH * MNODES * MNODES + 255) / 256, 256, 0, s1>>>(out, BATCH * MNODES * MNODES);
    cudaEventRecord(e1, s1);

    // join, then tail
    cudaStreamWaitEvent(0, e1, 0);
    uv_k<<<512, 256, 65536>>>(adj_b1);
    pair_k<<<dim3(BATCH, 4), 256>>>(adj_W2, adj_b2, gu, n_nodes, out);
}